// round 9
// baseline (speedup 1.0000x reference)
#include <cuda_runtime.h>
#include <cuda_bf16.h>

// Problem constants
#define T   2048
#define D   2048
#define NH  16
#define DH  128
#define DRH 64
#define DC  512
#define QKD 192   // DH + DRH

// -------- scratch (device globals; no allocation allowed) --------
__device__ float g_ckv[(size_t)T * DC];
__device__ float g_cq [(size_t)T * DC];
__device__ float g_q  [(size_t)NH * T * QKD];
__device__ float g_k  [(size_t)NH * T * QKD];
__device__ float g_v  [(size_t)NH * T * DH];
__device__ float g_kr [(size_t)T * DRH];
__device__ float g_logits[(size_t)NH * T * T];
__device__ float g_attn[(size_t)T * NH * DH];
__device__ float g_wot [(size_t)D * NH * DH];

typedef unsigned long long ull;

__device__ __forceinline__ void ffma2(ull& d, ull a, ull b) {
    asm("fma.rn.f32x2 %0, %1, %2, %0;" : "+l"(d) : "l"(a), "l"(b));
}
__device__ __forceinline__ ull dup2(float x) {
    ull r;
    asm("mov.b64 %0, {%1, %1};" : "=l"(r) : "f"(x));
    return r;
}
union F2u { ull u; float2 f; };

// ============================================================
// TF32 tensor-core GEMM: 128x128x16 tile, 8 warps, warp = 64x32
// mma.sync.aligned.m16n8k8 tf32, fp32 accumulate.
// CMODE: 0 = plain, 1 = skip upper-triangular tiles (causal logits),
//        2 = start k-loop at bm (causal S^T V).
// ============================================================

__device__ __forceinline__ unsigned f2tf(float x) {
    unsigned r;
    asm("cvt.rna.tf32.f32 %0, %1;" : "=r"(r) : "f"(x));
    return r;
}

__device__ __forceinline__ void mma8(float* c, const unsigned* a, const unsigned* b) {
    asm("mma.sync.aligned.m16n8k8.row.col.f32.tf32.tf32.f32 "
        "{%0,%1,%2,%3}, {%4,%5,%6,%7}, {%8,%9}, {%0,%1,%2,%3};"
        : "+f"(c[0]), "+f"(c[1]), "+f"(c[2]), "+f"(c[3])
        : "r"(a[0]), "r"(a[1]), "r"(a[2]), "r"(a[3]), "r"(b[0]), "r"(b[1]));
}

__device__ __forceinline__ int a_word(int m, int k) {
    int t = (m & 7) * 4 + (k & 3);
    int r = (((k & 7) >> 2) << 1) | ((m >> 3) & 1);
    int k8 = k >> 3;
    int w = (t * 4) ^ (((t >> 2) & 7) << 2);
    return (k8 * 8 + (m >> 4)) * 128 + w + (r ^ k8);
}
__device__ __forceinline__ int b_word(int n, int k) {
    int t = (n & 7) * 4 + (k & 3);
    int r = (k & 7) >> 2;
    int k8 = k >> 3;
    int w = (t * 2) ^ (((t >> 2) & 7) << 1) ^ (k8 << 1);
    return (k8 * 16 + (n >> 3)) * 64 + w + r;
}

template<bool TN, int CMODE>
__global__ __launch_bounds__(256, 2) void gemm_tf32(
    const float* __restrict__ A, const float* __restrict__ B, float* __restrict__ C,
    int K, int lda, int ldb, int ldc,
    long long sA, long long sB, long long sC)
{
    __shared__ __align__(16) unsigned As[2][2048];
    __shared__ __align__(16) unsigned Bs[2][2048];
    const int bm = blockIdx.y * 128;
    const int bn = blockIdx.x * 128;
    if (CMODE == 1 && bn > bm) return;   // fully-masked tile: softmax writes zeros
    A += (long long)blockIdx.z * sA;
    B += (long long)blockIdx.z * sB;
    C += (long long)blockIdx.z * sC;
    if (CMODE == 2) {                    // S[t,l] = 0 for t < l  ->  start k at bm
        if (TN) { A += (long long)bm * lda; B += (long long)bm * ldb; }
        else    { A += bm; B += bm; }
        K -= bm;
    }
    const int tid = threadIdx.x;
    const int lane = tid & 31;
    const int wm = ((tid >> 5) & 1) * 4;
    const int wn = ((tid >> 5) >> 1) * 4;

    float acc[4][4][4];
#pragma unroll
    for (int x = 0; x < 4; ++x)
#pragma unroll
        for (int y = 0; y < 4; ++y)
#pragma unroll
            for (int z = 0; z < 4; ++z) acc[x][y][z] = 0.0f;

    int r0, c0;
    if (!TN) { r0 = tid >> 2; c0 = (tid & 3) * 4; }
    else     { r0 = tid & 15; c0 = (tid >> 4) * 8; }

    const int ntl = K / 16;
    float4 a0, a1, b0, b1;

    if (!TN) {
        a0 = *(const float4*)(A + (long long)(bm + r0) * lda + c0);
        a1 = *(const float4*)(A + (long long)(bm + r0 + 64) * lda + c0);
        b0 = *(const float4*)(B + (long long)(bn + r0) * ldb + c0);
        b1 = *(const float4*)(B + (long long)(bn + r0 + 64) * ldb + c0);
    } else {
        a0 = *(const float4*)(A + (long long)r0 * lda + bm + c0);
        a1 = *(const float4*)(A + (long long)r0 * lda + bm + c0 + 4);
        b0 = *(const float4*)(B + (long long)r0 * ldb + bn + c0);
        b1 = *(const float4*)(B + (long long)r0 * ldb + bn + c0 + 4);
    }

    int buf = 0;
    {
        const float* av0 = (const float*)&a0;
        const float* av1 = (const float*)&a1;
        const float* bv0 = (const float*)&b0;
        const float* bv1 = (const float*)&b1;
        if (!TN) {
#pragma unroll
            for (int j = 0; j < 4; ++j) {
                As[0][a_word(r0,      c0 + j)] = f2tf(av0[j]);
                As[0][a_word(r0 + 64, c0 + j)] = f2tf(av1[j]);
                Bs[0][b_word(r0,      c0 + j)] = f2tf(bv0[j]);
                Bs[0][b_word(r0 + 64, c0 + j)] = f2tf(bv1[j]);
            }
        } else {
#pragma unroll
            for (int j = 0; j < 4; ++j) {
                As[0][a_word(c0 + j,     r0)] = f2tf(av0[j]);
                As[0][a_word(c0 + 4 + j, r0)] = f2tf(av1[j]);
                Bs[0][b_word(c0 + j,     r0)] = f2tf(bv0[j]);
                Bs[0][b_word(c0 + 4 + j, r0)] = f2tf(bv1[j]);
            }
        }
    }
    __syncthreads();

    for (int it = 0; it < ntl; ++it) {
        if (it + 1 < ntl) {
            const int k0 = (it + 1) * 16;
            if (!TN) {
                a0 = *(const float4*)(A + (long long)(bm + r0) * lda + k0 + c0);
                a1 = *(const float4*)(A + (long long)(bm + r0 + 64) * lda + k0 + c0);
                b0 = *(const float4*)(B + (long long)(bn + r0) * ldb + k0 + c0);
                b1 = *(const float4*)(B + (long long)(bn + r0 + 64) * ldb + k0 + c0);
            } else {
                a0 = *(const float4*)(A + (long long)(k0 + r0) * lda + bm + c0);
                a1 = *(const float4*)(A + (long long)(k0 + r0) * lda + bm + c0 + 4);
                b0 = *(const float4*)(B + (long long)(k0 + r0) * ldb + bn + c0);
                b1 = *(const float4*)(B + (long long)(k0 + r0) * ldb + bn + c0 + 4);
            }
        }
        const unsigned* Asb = As[buf];
        const unsigned* Bsb = Bs[buf];
#pragma unroll
        for (int k8 = 0; k8 < 2; ++k8) {
            unsigned af[4][4];
            unsigned bfm[4][2];
#pragma unroll
            for (int mt = 0; mt < 4; ++mt) {
                uint4 w = *(const uint4*)&Asb[(k8 * 8 + wm + mt) * 128 +
                                              ((lane * 4) ^ (((lane >> 2) & 7) << 2))];
                af[mt][0] = k8 ? w.y : w.x;
                af[mt][1] = k8 ? w.x : w.y;
                af[mt][2] = k8 ? w.w : w.z;
                af[mt][3] = k8 ? w.z : w.w;
            }
#pragma unroll
            for (int nt = 0; nt < 4; ++nt) {
                uint2 w = *(const uint2*)&Bsb[(k8 * 16 + wn + nt) * 64 +
                                              ((lane * 2) ^ (((lane >> 2) & 7) << 1) ^ (k8 << 1))];
                bfm[nt][0] = w.x;
                bfm[nt][1] = w.y;
            }
#pragma unroll
            for (int mt = 0; mt < 4; ++mt)
#pragma unroll
                for (int nt = 0; nt < 4; ++nt)
                    mma8(acc[mt][nt], af[mt], bfm[nt]);
        }
        if (it + 1 < ntl) {
            buf ^= 1;
            const float* av0 = (const float*)&a0;
            const float* av1 = (const float*)&a1;
            const float* bv0 = (const float*)&b0;
            const float* bv1 = (const float*)&b1;
            if (!TN) {
#pragma unroll
                for (int j = 0; j < 4; ++j) {
                    As[buf][a_word(r0,      c0 + j)] = f2tf(av0[j]);
                    As[buf][a_word(r0 + 64, c0 + j)] = f2tf(av1[j]);
                    Bs[buf][b_word(r0,      c0 + j)] = f2tf(bv0[j]);
                    Bs[buf][b_word(r0 + 64, c0 + j)] = f2tf(bv1[j]);
                }
            } else {
#pragma unroll
                for (int j = 0; j < 4; ++j) {
                    As[buf][a_word(c0 + j,     r0)] = f2tf(av0[j]);
                    As[buf][a_word(c0 + 4 + j, r0)] = f2tf(av1[j]);
                    Bs[buf][b_word(c0 + j,     r0)] = f2tf(bv0[j]);
                    Bs[buf][b_word(c0 + 4 + j, r0)] = f2tf(bv1[j]);
                }
            }
            __syncthreads();
        }
    }

    const int gid = lane >> 2;
    const int tig = lane & 3;
#pragma unroll
    for (int mt = 0; mt < 4; ++mt) {
        const long long row = bm + (wm + mt) * 16 + gid;
#pragma unroll
        for (int nt = 0; nt < 4; ++nt) {
            const int col = bn + (wn + nt) * 8 + tig * 2;
            *(float2*)(C + row * ldc + col) = make_float2(acc[mt][nt][0], acc[mt][nt][1]);
            *(float2*)(C + (row + 8) * ldc + col) = make_float2(acc[mt][nt][2], acc[mt][nt][3]);
        }
    }
}

// ============================================================
// 64x64 fp32 GEMM (N=64 cases: k_r, q_r) — FFMA2 mainloop
// ============================================================
#define SM_ 64
#define SK_ 16
__global__ __launch_bounds__(256) void gemm_nt64(
    const float* __restrict__ A, const float* __restrict__ B, float* __restrict__ C,
    int K, int lda, int ldb, int ldc,
    long long sA, long long sB, long long sC)
{
    __shared__ float As[SK_][SM_];
    __shared__ float Bs[SK_][SM_];
    A += (long long)blockIdx.z * sA;
    B += (long long)blockIdx.z * sB;
    C += (long long)blockIdx.z * sC;
    const int bm = blockIdx.y * SM_;
    const int bn = blockIdx.x * SM_;
    const int tid = threadIdx.x;
    const int tx = tid & 15;
    const int ty = tid >> 4;
    const int lrow = tid >> 2;
    const int lcol = (tid & 3) * 4;

    ull acc2[2][4] = {};

    for (int k0 = 0; k0 < K; k0 += SK_) {
        float4 a = *(const float4*)(A + (long long)(bm + lrow) * lda + k0 + lcol);
        float4 b = *(const float4*)(B + (long long)(bn + lrow) * ldb + k0 + lcol);
        __syncthreads();
        As[lcol + 0][lrow] = a.x; As[lcol + 1][lrow] = a.y;
        As[lcol + 2][lrow] = a.z; As[lcol + 3][lrow] = a.w;
        Bs[lcol + 0][lrow] = b.x; Bs[lcol + 1][lrow] = b.y;
        Bs[lcol + 2][lrow] = b.z; Bs[lcol + 3][lrow] = b.w;
        __syncthreads();
#pragma unroll
        for (int kk = 0; kk < SK_; ++kk) {
            float4 av = *(const float4*)(&As[kk][ty * 4]);
            float4 bv = *(const float4*)(&Bs[kk][tx * 4]);
            ull ap[2];
            ap[0] = ((const ull*)&av)[0];
            ap[1] = ((const ull*)&av)[1];
            ull bb[4];
            bb[0] = dup2(bv.x); bb[1] = dup2(bv.y);
            bb[2] = dup2(bv.z); bb[3] = dup2(bv.w);
#pragma unroll
            for (int p = 0; p < 2; ++p)
#pragma unroll
                for (int j = 0; j < 4; ++j)
                    ffma2(acc2[p][j], ap[p], bb[j]);
        }
    }

#pragma unroll
    for (int p = 0; p < 2; ++p) {
#pragma unroll
        for (int half = 0; half < 2; ++half) {
            const int crow = bm + ty * 4 + p * 2 + half;
            F2u v0, v1, v2, v3;
            v0.u = acc2[p][0]; v1.u = acc2[p][1];
            v2.u = acc2[p][2]; v3.u = acc2[p][3];
            float4 o = half ? make_float4(v0.f.y, v1.f.y, v2.f.y, v3.f.y)
                            : make_float4(v0.f.x, v1.f.x, v2.f.x, v3.f.x);
            *(float4*)(C + (long long)crow * ldc + bn + tx * 4) = o;
        }
    }
}

// ============================================================
// Elementwise kernels
// ============================================================
__global__ void rope_q_kernel(float* __restrict__ q, const float* __restrict__ freqs)
{
    int idx = blockIdx.x * blockDim.x + threadIdx.x;   // NH*T*32
    int i = idx & 31;
    int t = (idx >> 5) & (T - 1);
    int n = idx >> 16;
    float ang = freqs[t * (DRH / 2) + i];
    float c, s;
    __sincosf(ang, &s, &c);
    float* base = q + ((size_t)(n * T + t)) * QKD + DH;
    float re = base[i], im = base[i + 32];
    base[i]      = re * c - im * s;
    base[i + 32] = re * s + im * c;
}

__global__ void rope_k_bcast_kernel(const float* __restrict__ kr, float* __restrict__ kbuf,
                                    const float* __restrict__ freqs)
{
    int idx = blockIdx.x * blockDim.x + threadIdx.x;   // T*32
    int i = idx & 31;
    int t = idx >> 5;
    float ang = freqs[t * (DRH / 2) + i];
    float c, s;
    __sincosf(ang, &s, &c);
    float re = kr[t * DRH + i], im = kr[t * DRH + 32 + i];
    const float inv_nh = 1.0f / (float)NH;
    float rr = (re * c - im * s) * inv_nh;
    float ri = (re * s + im * c) * inv_nh;
#pragma unroll
    for (int n = 0; n < NH; ++n) {
        float* b = kbuf + ((size_t)(n * T + t)) * QKD + DH;
        b[i]      = rr;
        b[i + 32] = ri;
    }
}

__global__ void wo_transpose_kernel(const float* __restrict__ wo, float* __restrict__ wt)
{
    int idx = blockIdx.x * blockDim.x + threadIdx.x;   // D * NH * DH
    int j = idx & (NH * DH - 1);
    int d = idx >> 11;
    int n = j >> 7;
    int e = j & (DH - 1);
    wt[idx] = wo[(size_t)d * (DH * NH) + e * NH + n];
}

// Causal softmax: row t over l, analytic mask (l<=t valid), zeros elsewhere.
__global__ __launch_bounds__(256) void softmax_kernel(
    float* __restrict__ logits, float scale)
{
    const int t = blockIdx.x;
    const int n = blockIdx.y;
    float* __restrict__ row = logits + ((size_t)n * T + t) * T;
    const int tid = threadIdx.x;
    const int wbase = tid & ~31;

    float v[8];
    float mx = -1e30f;
#pragma unroll
    for (int j = 0; j < 8; ++j) {
        const int l = tid + j * 256;
        if (wbase + j * 256 > t) {           // whole warp-chunk masked: skip load
            v[j] = -1e30f;
        } else {
            float x = row[l];
            v[j] = (l <= t) ? x * scale : -1e30f;
        }
        mx = fmaxf(mx, v[j]);
    }
    __shared__ float redm[8], reds[8];
#pragma unroll
    for (int o = 16; o; o >>= 1) mx = fmaxf(mx, __shfl_xor_sync(0xffffffffu, mx, o));
    if ((tid & 31) == 0) redm[tid >> 5] = mx;
    __syncthreads();
    mx = redm[0];
#pragma unroll
    for (int w = 1; w < 8; ++w) mx = fmaxf(mx, redm[w]);

    float sum = 0.0f;
#pragma unroll
    for (int j = 0; j < 8; ++j) {
        if (v[j] > -1e29f) {
            v[j] = __expf(v[j] - mx);
            sum += v[j];
        } else {
            v[j] = 0.0f;
        }
    }
#pragma unroll
    for (int o = 16; o; o >>= 1) sum += __shfl_xor_sync(0xffffffffu, sum, o);
    if ((tid & 31) == 0) reds[tid >> 5] = sum;
    __syncthreads();
    sum = reds[0];
#pragma unroll
    for (int w = 1; w < 8; ++w) sum += reds[w];

    float inv = 1.0f / sum;
#pragma unroll
    for (int j = 0; j < 8; ++j)
        row[tid + j * 256] = v[j] * inv;
}

// ============================================================
// Launch
// ============================================================
extern "C" void kernel_launch(void* const* d_in, const int* in_sizes, int n_in,
                              void* d_out, int out_size)
{
    const float* h     = (const float*)d_in[0];
    const float* freqs = (const float*)d_in[1];
    const float* w_dkv = (const float*)d_in[3];
    const float* w_uk  = (const float*)d_in[4];
    const float* w_uv  = (const float*)d_in[5];
    const float* w_dq  = (const float*)d_in[6];
    const float* w_uq  = (const float*)d_in[7];
    const float* w_qr  = (const float*)d_in[8];
    const float* w_kr  = (const float*)d_in[9];
    const float* w_o   = (const float*)d_in[10];
    float* out = (float*)d_out;
    (void)in_sizes; (void)n_in; (void)out_size;

    float *ckv, *cq, *q, *k, *v, *kr, *logits, *attn, *wot;
    cudaGetSymbolAddress((void**)&ckv,    g_ckv);
    cudaGetSymbolAddress((void**)&cq,     g_cq);
    cudaGetSymbolAddress((void**)&q,      g_q);
    cudaGetSymbolAddress((void**)&k,      g_k);
    cudaGetSymbolAddress((void**)&v,      g_v);
    cudaGetSymbolAddress((void**)&kr,     g_kr);
    cudaGetSymbolAddress((void**)&logits, g_logits);
    cudaGetSymbolAddress((void**)&attn,   g_attn);
    cudaGetSymbolAddress((void**)&wot,    g_wot);

    const dim3 blk(256);
    const long long sQ = (long long)T * QKD;

    // Latents: c_kv, c_q = h @ W^T
    gemm_tf32<false, 0><<<dim3(DC / 128, T / 128, 1), blk>>>(h, w_dkv, ckv, D, D, D, DC, 0, 0, 0);
    gemm_tf32<false, 0><<<dim3(DC / 128, T / 128, 1), blk>>>(h, w_dq,  cq,  D, D, D, DC, 0, 0, 0);
    // k_r (pre-rope): N=64, fp32
    gemm_nt64<<<dim3(1, T / SM_, 1), blk>>>(h, w_kr, kr, D, D, D, DRH, 0, 0, 0);

    // Per-head up-projections
    gemm_tf32<false, 0><<<dim3(1, T / 128, NH), blk>>>(ckv, w_uk, k, DC, DC, NH * DC, QKD, 0, DC, sQ);
    gemm_tf32<false, 0><<<dim3(1, T / 128, NH), blk>>>(ckv, w_uv, v, DC, DC, NH * DC, DH,  0, DC, (long long)T * DH);
    gemm_tf32<false, 0><<<dim3(1, T / 128, NH), blk>>>(cq,  w_uq, q, DC, DC, NH * DC, QKD, 0, DC, sQ);
    // q_r: N=64, fp32
    gemm_nt64<<<dim3(1, T / SM_, NH), blk>>>(cq, w_qr, q + DH, DC, DC, NH * DC, QKD, 0, DC, sQ);

    // Rope
    rope_q_kernel<<<(NH * T * 32) / 256, 256>>>(q, freqs);
    rope_k_bcast_kernel<<<(T * 32) / 256, 256>>>(kr, k, freqs);

    // logits[n,t,l] = q . k  — skip fully-masked upper tiles
    gemm_tf32<false, 1><<<dim3(T / 128, T / 128, NH), blk>>>(q, k, logits, QKD, QKD, QKD, T, sQ, sQ, (long long)T * T);

    // causal softmax, scale = 1/sqrt(192); writes exact zeros for l > t
    softmax_kernel<<<dim3(T, NH), 256>>>(logits, 0.07216878364870323f);

    // out[n,l,e] = sum_{t>=l} S[n,t,l] v[n,t,e]  — k-loop starts at bm
    gemm_tf32<true, 2><<<dim3(1, T / 128, NH), blk>>>(logits, v, attn, T, T, DH, NH * DH,
                                                      (long long)T * T, (long long)T * DH, DH);

    // w_o permute then final projection
    wo_transpose_kernel<<<(D * NH * DH) / 256, 256>>>(w_o, wot);
    gemm_tf32<false, 0><<<dim3(D / 128, T / 128, 1), blk>>>(attn, wot, out, NH * DH, NH * DH, NH * DH, D, 0, 0, 0);
}

// round 10
// speedup vs baseline: 1.2201x; 1.2201x over previous
#include <cuda_runtime.h>
#include <cuda_bf16.h>

// Problem constants
#define T   2048
#define D   2048
#define NH  16
#define DH  128
#define DRH 64
#define DC  512
#define QKD 192   // DH + DRH

// -------- scratch (device globals; no allocation allowed) --------
__device__ float g_ckv[(size_t)T * DC];
__device__ float g_cq [(size_t)T * DC];
__device__ float g_q  [(size_t)NH * T * QKD];
__device__ float g_k  [(size_t)NH * T * QKD];
__device__ float g_v  [(size_t)NH * T * DH];
__device__ float g_kr [(size_t)T * DRH];
__device__ float g_logits[(size_t)NH * T * T];
__device__ float g_attn[(size_t)T * NH * DH];
__device__ float g_wot [(size_t)D * NH * DH];

typedef unsigned long long ull;

__device__ __forceinline__ void ffma2(ull& d, ull a, ull b) {
    asm("fma.rn.f32x2 %0, %1, %2, %0;" : "+l"(d) : "l"(a), "l"(b));
}
__device__ __forceinline__ ull dup2(float x) {
    ull r;
    asm("mov.b64 %0, {%1, %1};" : "=l"(r) : "f"(x));
    return r;
}
union F2u { ull u; float2 f; };

// ============================================================
// TF32 tensor-core GEMM: 128x128x16 tile, 8 warps, warp = 64x32
// mma.sync.aligned.m16n8k8 tf32, fp32 accumulate.
// CMODE: 0 = plain, 1 = skip upper-triangular tiles (causal logits),
//        2 = start k-loop at bm (causal S^T V).
// ============================================================

__device__ __forceinline__ unsigned f2tf(float x) {
    unsigned r;
    asm("cvt.rna.tf32.f32 %0, %1;" : "=r"(r) : "f"(x));
    return r;
}

__device__ __forceinline__ void mma8(float* c, const unsigned* a, const unsigned* b) {
    asm("mma.sync.aligned.m16n8k8.row.col.f32.tf32.tf32.f32 "
        "{%0,%1,%2,%3}, {%4,%5,%6,%7}, {%8,%9}, {%0,%1,%2,%3};"
        : "+f"(c[0]), "+f"(c[1]), "+f"(c[2]), "+f"(c[3])
        : "r"(a[0]), "r"(a[1]), "r"(a[2]), "r"(a[3]), "r"(b[0]), "r"(b[1]));
}

__device__ __forceinline__ int a_word(int m, int k) {
    int t = (m & 7) * 4 + (k & 3);
    int r = (((k & 7) >> 2) << 1) | ((m >> 3) & 1);
    int k8 = k >> 3;
    int w = (t * 4) ^ (((t >> 2) & 7) << 2);
    return (k8 * 8 + (m >> 4)) * 128 + w + (r ^ k8);
}
__device__ __forceinline__ int b_word(int n, int k) {
    int t = (n & 7) * 4 + (k & 3);
    int r = (k & 7) >> 2;
    int k8 = k >> 3;
    int w = (t * 2) ^ (((t >> 2) & 7) << 1) ^ (k8 << 1);
    return (k8 * 16 + (n >> 3)) * 64 + w + r;
}

template<bool TN, int CMODE>
__global__ __launch_bounds__(256) void gemm_tf32(
    const float* __restrict__ A, const float* __restrict__ B, float* __restrict__ C,
    int K, int lda, int ldb, int ldc,
    long long sA, long long sB, long long sC)
{
    __shared__ __align__(16) unsigned As[2][2048];
    __shared__ __align__(16) unsigned Bs[2][2048];
    const int bm = blockIdx.y * 128;
    const int bn = blockIdx.x * 128;
    if (CMODE == 1 && bn > bm) return;   // fully-masked tile: softmax writes zeros
    A += (long long)blockIdx.z * sA;
    B += (long long)blockIdx.z * sB;
    C += (long long)blockIdx.z * sC;
    if (CMODE == 2) {                    // S[t,l] = 0 for t < l  ->  start k at bm
        if (TN) { A += (long long)bm * lda; B += (long long)bm * ldb; }
        else    { A += bm; B += bm; }
        K -= bm;
    }
    const int tid = threadIdx.x;
    const int lane = tid & 31;
    const int wm = ((tid >> 5) & 1) * 4;
    const int wn = ((tid >> 5) >> 1) * 4;

    float acc[4][4][4];
#pragma unroll
    for (int x = 0; x < 4; ++x)
#pragma unroll
        for (int y = 0; y < 4; ++y)
#pragma unroll
            for (int z = 0; z < 4; ++z) acc[x][y][z] = 0.0f;

    int r0, c0;
    if (!TN) { r0 = tid >> 2; c0 = (tid & 3) * 4; }
    else     { r0 = tid & 15; c0 = (tid >> 4) * 8; }

    const int ntl = K / 16;
    float4 a0, a1, b0, b1;

    if (!TN) {
        a0 = *(const float4*)(A + (long long)(bm + r0) * lda + c0);
        a1 = *(const float4*)(A + (long long)(bm + r0 + 64) * lda + c0);
        b0 = *(const float4*)(B + (long long)(bn + r0) * ldb + c0);
        b1 = *(const float4*)(B + (long long)(bn + r0 + 64) * ldb + c0);
    } else {
        a0 = *(const float4*)(A + (long long)r0 * lda + bm + c0);
        a1 = *(const float4*)(A + (long long)r0 * lda + bm + c0 + 4);
        b0 = *(const float4*)(B + (long long)r0 * ldb + bn + c0);
        b1 = *(const float4*)(B + (long long)r0 * ldb + bn + c0 + 4);
    }

    int buf = 0;
    {
        const float* av0 = (const float*)&a0;
        const float* av1 = (const float*)&a1;
        const float* bv0 = (const float*)&b0;
        const float* bv1 = (const float*)&b1;
        if (!TN) {
#pragma unroll
            for (int j = 0; j < 4; ++j) {
                As[0][a_word(r0,      c0 + j)] = f2tf(av0[j]);
                As[0][a_word(r0 + 64, c0 + j)] = f2tf(av1[j]);
                Bs[0][b_word(r0,      c0 + j)] = f2tf(bv0[j]);
                Bs[0][b_word(r0 + 64, c0 + j)] = f2tf(bv1[j]);
            }
        } else {
#pragma unroll
            for (int j = 0; j < 4; ++j) {
                As[0][a_word(c0 + j,     r0)] = f2tf(av0[j]);
                As[0][a_word(c0 + 4 + j, r0)] = f2tf(av1[j]);
                Bs[0][b_word(c0 + j,     r0)] = f2tf(bv0[j]);
                Bs[0][b_word(c0 + 4 + j, r0)] = f2tf(bv1[j]);
            }
        }
    }
    __syncthreads();

    for (int it = 0; it < ntl; ++it) {
        if (it + 1 < ntl) {
            const int k0 = (it + 1) * 16;
            if (!TN) {
                a0 = *(const float4*)(A + (long long)(bm + r0) * lda + k0 + c0);
                a1 = *(const float4*)(A + (long long)(bm + r0 + 64) * lda + k0 + c0);
                b0 = *(const float4*)(B + (long long)(bn + r0) * ldb + k0 + c0);
                b1 = *(const float4*)(B + (long long)(bn + r0 + 64) * ldb + k0 + c0);
            } else {
                a0 = *(const float4*)(A + (long long)(k0 + r0) * lda + bm + c0);
                a1 = *(const float4*)(A + (long long)(k0 + r0) * lda + bm + c0 + 4);
                b0 = *(const float4*)(B + (long long)(k0 + r0) * ldb + bn + c0);
                b1 = *(const float4*)(B + (long long)(k0 + r0) * ldb + bn + c0 + 4);
            }
        }
        const unsigned* Asb = As[buf];
        const unsigned* Bsb = Bs[buf];
#pragma unroll
        for (int k8 = 0; k8 < 2; ++k8) {
            unsigned af[4][4];
            unsigned bfm[4][2];
#pragma unroll
            for (int mt = 0; mt < 4; ++mt) {
                uint4 w = *(const uint4*)&Asb[(k8 * 8 + wm + mt) * 128 +
                                              ((lane * 4) ^ (((lane >> 2) & 7) << 2))];
                af[mt][0] = k8 ? w.y : w.x;
                af[mt][1] = k8 ? w.x : w.y;
                af[mt][2] = k8 ? w.w : w.z;
                af[mt][3] = k8 ? w.z : w.w;
            }
#pragma unroll
            for (int nt = 0; nt < 4; ++nt) {
                uint2 w = *(const uint2*)&Bsb[(k8 * 16 + wn + nt) * 64 +
                                              ((lane * 2) ^ (((lane >> 2) & 7) << 1) ^ (k8 << 1))];
                bfm[nt][0] = w.x;
                bfm[nt][1] = w.y;
            }
#pragma unroll
            for (int mt = 0; mt < 4; ++mt)
#pragma unroll
                for (int nt = 0; nt < 4; ++nt)
                    mma8(acc[mt][nt], af[mt], bfm[nt]);
        }
        if (it + 1 < ntl) {
            buf ^= 1;
            const float* av0 = (const float*)&a0;
            const float* av1 = (const float*)&a1;
            const float* bv0 = (const float*)&b0;
            const float* bv1 = (const float*)&b1;
            if (!TN) {
#pragma unroll
                for (int j = 0; j < 4; ++j) {
                    As[buf][a_word(r0,      c0 + j)] = f2tf(av0[j]);
                    As[buf][a_word(r0 + 64, c0 + j)] = f2tf(av1[j]);
                    Bs[buf][b_word(r0,      c0 + j)] = f2tf(bv0[j]);
                    Bs[buf][b_word(r0 + 64, c0 + j)] = f2tf(bv1[j]);
                }
            } else {
#pragma unroll
                for (int j = 0; j < 4; ++j) {
                    As[buf][a_word(c0 + j,     r0)] = f2tf(av0[j]);
                    As[buf][a_word(c0 + 4 + j, r0)] = f2tf(av1[j]);
                    Bs[buf][b_word(c0 + j,     r0)] = f2tf(bv0[j]);
                    Bs[buf][b_word(c0 + 4 + j, r0)] = f2tf(bv1[j]);
                }
            }
            __syncthreads();
        }
    }

    const int gid = lane >> 2;
    const int tig = lane & 3;
#pragma unroll
    for (int mt = 0; mt < 4; ++mt) {
        const long long row = bm + (wm + mt) * 16 + gid;
#pragma unroll
        for (int nt = 0; nt < 4; ++nt) {
            const int col = bn + (wn + nt) * 8 + tig * 2;
            *(float2*)(C + row * ldc + col) = make_float2(acc[mt][nt][0], acc[mt][nt][1]);
            *(float2*)(C + (row + 8) * ldc + col) = make_float2(acc[mt][nt][2], acc[mt][nt][3]);
        }
    }
}

// ============================================================
// 64x64 fp32 GEMM (N=64 cases: k_r, q_r) — FFMA2 mainloop
// ============================================================
#define SM_ 64
#define SK_ 16
__global__ __launch_bounds__(256) void gemm_nt64(
    const float* __restrict__ A, const float* __restrict__ B, float* __restrict__ C,
    int K, int lda, int ldb, int ldc,
    long long sA, long long sB, long long sC)
{
    __shared__ float As[SK_][SM_];
    __shared__ float Bs[SK_][SM_];
    A += (long long)blockIdx.z * sA;
    B += (long long)blockIdx.z * sB;
    C += (long long)blockIdx.z * sC;
    const int bm = blockIdx.y * SM_;
    const int bn = blockIdx.x * SM_;
    const int tid = threadIdx.x;
    const int tx = tid & 15;
    const int ty = tid >> 4;
    const int lrow = tid >> 2;
    const int lcol = (tid & 3) * 4;

    ull acc2[2][4] = {};

    for (int k0 = 0; k0 < K; k0 += SK_) {
        float4 a = *(const float4*)(A + (long long)(bm + lrow) * lda + k0 + lcol);
        float4 b = *(const float4*)(B + (long long)(bn + lrow) * ldb + k0 + lcol);
        __syncthreads();
        As[lcol + 0][lrow] = a.x; As[lcol + 1][lrow] = a.y;
        As[lcol + 2][lrow] = a.z; As[lcol + 3][lrow] = a.w;
        Bs[lcol + 0][lrow] = b.x; Bs[lcol + 1][lrow] = b.y;
        Bs[lcol + 2][lrow] = b.z; Bs[lcol + 3][lrow] = b.w;
        __syncthreads();
#pragma unroll
        for (int kk = 0; kk < SK_; ++kk) {
            float4 av = *(const float4*)(&As[kk][ty * 4]);
            float4 bv = *(const float4*)(&Bs[kk][tx * 4]);
            ull ap[2];
            ap[0] = ((const ull*)&av)[0];
            ap[1] = ((const ull*)&av)[1];
            ull bb[4];
            bb[0] = dup2(bv.x); bb[1] = dup2(bv.y);
            bb[2] = dup2(bv.z); bb[3] = dup2(bv.w);
#pragma unroll
            for (int p = 0; p < 2; ++p)
#pragma unroll
                for (int j = 0; j < 4; ++j)
                    ffma2(acc2[p][j], ap[p], bb[j]);
        }
    }

#pragma unroll
    for (int p = 0; p < 2; ++p) {
#pragma unroll
        for (int half = 0; half < 2; ++half) {
            const int crow = bm + ty * 4 + p * 2 + half;
            F2u v0, v1, v2, v3;
            v0.u = acc2[p][0]; v1.u = acc2[p][1];
            v2.u = acc2[p][2]; v3.u = acc2[p][3];
            float4 o = half ? make_float4(v0.f.y, v1.f.y, v2.f.y, v3.f.y)
                            : make_float4(v0.f.x, v1.f.x, v2.f.x, v3.f.x);
            *(float4*)(C + (long long)crow * ldc + bn + tx * 4) = o;
        }
    }
}

// ============================================================
// Elementwise kernels
// ============================================================
__global__ void rope_q_kernel(float* __restrict__ q, const float* __restrict__ freqs)
{
    int idx = blockIdx.x * blockDim.x + threadIdx.x;   // NH*T*32
    int i = idx & 31;
    int t = (idx >> 5) & (T - 1);
    int n = idx >> 16;
    float ang = freqs[t * (DRH / 2) + i];
    float c, s;
    __sincosf(ang, &s, &c);
    float* base = q + ((size_t)(n * T + t)) * QKD + DH;
    float re = base[i], im = base[i + 32];
    base[i]      = re * c - im * s;
    base[i + 32] = re * s + im * c;
}

__global__ void rope_k_bcast_kernel(const float* __restrict__ kr, float* __restrict__ kbuf,
                                    const float* __restrict__ freqs)
{
    int idx = blockIdx.x * blockDim.x + threadIdx.x;   // T*32
    int i = idx & 31;
    int t = idx >> 5;
    float ang = freqs[t * (DRH / 2) + i];
    float c, s;
    __sincosf(ang, &s, &c);
    float re = kr[t * DRH + i], im = kr[t * DRH + 32 + i];
    const float inv_nh = 1.0f / (float)NH;
    float rr = (re * c - im * s) * inv_nh;
    float ri = (re * s + im * c) * inv_nh;
#pragma unroll
    for (int n = 0; n < NH; ++n) {
        float* b = kbuf + ((size_t)(n * T + t)) * QKD + DH;
        b[i]      = rr;
        b[i + 32] = ri;
    }
}

__global__ void wo_transpose_kernel(const float* __restrict__ wo, float* __restrict__ wt)
{
    int idx = blockIdx.x * blockDim.x + threadIdx.x;   // D * NH * DH
    int j = idx & (NH * DH - 1);
    int d = idx >> 11;
    int n = j >> 7;
    int e = j & (DH - 1);
    wt[idx] = wo[(size_t)d * (DH * NH) + e * NH + n];
}

// Causal softmax: row t over l, analytic mask (l<=t valid), zeros elsewhere.
__global__ __launch_bounds__(256) void softmax_kernel(
    float* __restrict__ logits, float scale)
{
    const int t = blockIdx.x;
    const int n = blockIdx.y;
    float* __restrict__ row = logits + ((size_t)n * T + t) * T;
    const int tid = threadIdx.x;
    const int wbase = tid & ~31;

    float v[8];
    float mx = -1e30f;
#pragma unroll
    for (int j = 0; j < 8; ++j) {
        const int l = tid + j * 256;
        if (wbase + j * 256 > t) {           // whole warp-chunk masked: skip load
            v[j] = -1e30f;
        } else {
            float x = row[l];
            v[j] = (l <= t) ? x * scale : -1e30f;
        }
        mx = fmaxf(mx, v[j]);
    }
    __shared__ float redm[8], reds[8];
#pragma unroll
    for (int o = 16; o; o >>= 1) mx = fmaxf(mx, __shfl_xor_sync(0xffffffffu, mx, o));
    if ((tid & 31) == 0) redm[tid >> 5] = mx;
    __syncthreads();
    mx = redm[0];
#pragma unroll
    for (int w = 1; w < 8; ++w) mx = fmaxf(mx, redm[w]);

    float sum = 0.0f;
#pragma unroll
    for (int j = 0; j < 8; ++j) {
        if (v[j] > -1e29f) {
            v[j] = __expf(v[j] - mx);
            sum += v[j];
        } else {
            v[j] = 0.0f;
        }
    }
#pragma unroll
    for (int o = 16; o; o >>= 1) sum += __shfl_xor_sync(0xffffffffu, sum, o);
    if ((tid & 31) == 0) reds[tid >> 5] = sum;
    __syncthreads();
    sum = reds[0];
#pragma unroll
    for (int w = 1; w < 8; ++w) sum += reds[w];

    float inv = 1.0f / sum;
#pragma unroll
    for (int j = 0; j < 8; ++j)
        row[tid + j * 256] = v[j] * inv;
}

// ============================================================
// Launch
// ============================================================
extern "C" void kernel_launch(void* const* d_in, const int* in_sizes, int n_in,
                              void* d_out, int out_size)
{
    const float* h     = (const float*)d_in[0];
    const float* freqs = (const float*)d_in[1];
    const float* w_dkv = (const float*)d_in[3];
    const float* w_uk  = (const float*)d_in[4];
    const float* w_uv  = (const float*)d_in[5];
    const float* w_dq  = (const float*)d_in[6];
    const float* w_uq  = (const float*)d_in[7];
    const float* w_qr  = (const float*)d_in[8];
    const float* w_kr  = (const float*)d_in[9];
    const float* w_o   = (const float*)d_in[10];
    float* out = (float*)d_out;
    (void)in_sizes; (void)n_in; (void)out_size;

    float *ckv, *cq, *q, *k, *v, *kr, *logits, *attn, *wot;
    cudaGetSymbolAddress((void**)&ckv,    g_ckv);
    cudaGetSymbolAddress((void**)&cq,     g_cq);
    cudaGetSymbolAddress((void**)&q,      g_q);
    cudaGetSymbolAddress((void**)&k,      g_k);
    cudaGetSymbolAddress((void**)&v,      g_v);
    cudaGetSymbolAddress((void**)&kr,     g_kr);
    cudaGetSymbolAddress((void**)&logits, g_logits);
    cudaGetSymbolAddress((void**)&attn,   g_attn);
    cudaGetSymbolAddress((void**)&wot,    g_wot);

    const dim3 blk(256);
    const long long sQ = (long long)T * QKD;

    // Latents: c_kv, c_q = h @ W^T
    gemm_tf32<false, 0><<<dim3(DC / 128, T / 128, 1), blk>>>(h, w_dkv, ckv, D, D, D, DC, 0, 0, 0);
    gemm_tf32<false, 0><<<dim3(DC / 128, T / 128, 1), blk>>>(h, w_dq,  cq,  D, D, D, DC, 0, 0, 0);
    // k_r (pre-rope): N=64, fp32
    gemm_nt64<<<dim3(1, T / SM_, 1), blk>>>(h, w_kr, kr, D, D, D, DRH, 0, 0, 0);

    // Per-head up-projections
    gemm_tf32<false, 0><<<dim3(1, T / 128, NH), blk>>>(ckv, w_uk, k, DC, DC, NH * DC, QKD, 0, DC, sQ);
    gemm_tf32<false, 0><<<dim3(1, T / 128, NH), blk>>>(ckv, w_uv, v, DC, DC, NH * DC, DH,  0, DC, (long long)T * DH);
    gemm_tf32<false, 0><<<dim3(1, T / 128, NH), blk>>>(cq,  w_uq, q, DC, DC, NH * DC, QKD, 0, DC, sQ);
    // q_r: N=64, fp32
    gemm_nt64<<<dim3(1, T / SM_, NH), blk>>>(cq, w_qr, q + DH, DC, DC, NH * DC, QKD, 0, DC, sQ);

    // Rope
    rope_q_kernel<<<(NH * T * 32) / 256, 256>>>(q, freqs);
    rope_k_bcast_kernel<<<(T * 32) / 256, 256>>>(kr, k, freqs);

    // logits[n,t,l] = q . k  — skip fully-masked upper tiles
    gemm_tf32<false, 1><<<dim3(T / 128, T / 128, NH), blk>>>(q, k, logits, QKD, QKD, QKD, T, sQ, sQ, (long long)T * T);

    // causal softmax, scale = 1/sqrt(192); writes exact zeros for l > t
    softmax_kernel<<<dim3(T, NH), 256>>>(logits, 0.07216878364870323f);

    // out[n,l,e] = sum_{t>=l} S[n,t,l] v[n,t,e]  — k-loop starts at bm
    gemm_tf32<true, 2><<<dim3(1, T / 128, NH), blk>>>(logits, v, attn, T, T, DH, NH * DH,
                                                      (long long)T * T, (long long)T * DH, DH);

    // w_o permute then final projection
    wo_transpose_kernel<<<(D * NH * DH) / 256, 256>>>(w_o, wot);
    gemm_tf32<false, 0><<<dim3(D / 128, T / 128, 1), blk>>>(attn, wot, out, NH * DH, NH * DH, NH * DH, D, 0, 0, 0);
}

// round 11
// speedup vs baseline: 1.3763x; 1.1280x over previous
#include <cuda_runtime.h>
#include <cuda_bf16.h>

// Problem constants
#define T   2048
#define D   2048
#define NH  16
#define DH  128
#define DRH 64
#define DC  512
#define QKD 192   // DH + DRH

// -------- scratch (device globals; no allocation allowed) --------
__device__ float g_ckv[(size_t)T * DC];
__device__ float g_cq [(size_t)T * DC];
__device__ float g_q  [(size_t)NH * T * QKD];
__device__ float g_k  [(size_t)NH * T * QKD];
__device__ float g_v  [(size_t)NH * T * DH];
__device__ float g_kr [(size_t)T * DRH];
__device__ float g_logits[(size_t)NH * T * T];
__device__ float g_attn[(size_t)T * NH * DH];
__device__ float g_wot [(size_t)D * NH * DH];

typedef unsigned long long ull;

__device__ __forceinline__ void ffma2(ull& d, ull a, ull b) {
    asm("fma.rn.f32x2 %0, %1, %2, %0;" : "+l"(d) : "l"(a), "l"(b));
}
__device__ __forceinline__ ull dup2(float x) {
    ull r;
    asm("mov.b64 %0, {%1, %1};" : "=l"(r) : "f"(x));
    return r;
}
union F2u { ull u; float2 f; };

// ============================================================
// TF32 tensor-core GEMM: 128x128x16 tile, 512 threads (16 warps),
// warp tile 32x32 (2 m16-tiles x 4 n8-tiles), fp32 accumulate.
// CMODE: 0 = plain, 1 = skip upper-triangular tiles (causal logits),
//        2 = start k-loop at bm (causal S^T V).
// ============================================================

__device__ __forceinline__ unsigned f2tf(float x) {
    unsigned r;
    asm("cvt.rna.tf32.f32 %0, %1;" : "=r"(r) : "f"(x));
    return r;
}

__device__ __forceinline__ void mma8(float* c, const unsigned* a, const unsigned* b) {
    asm("mma.sync.aligned.m16n8k8.row.col.f32.tf32.tf32.f32 "
        "{%0,%1,%2,%3}, {%4,%5,%6,%7}, {%8,%9}, {%0,%1,%2,%3};"
        : "+f"(c[0]), "+f"(c[1]), "+f"(c[2]), "+f"(c[3])
        : "r"(a[0]), "r"(a[1]), "r"(a[2]), "r"(a[3]), "r"(b[0]), "r"(b[1]));
}

__device__ __forceinline__ int a_word(int m, int k) {
    int t = (m & 7) * 4 + (k & 3);
    int r = (((k & 7) >> 2) << 1) | ((m >> 3) & 1);
    int k8 = k >> 3;
    int w = (t * 4) ^ (((t >> 2) & 7) << 2);
    return (k8 * 8 + (m >> 4)) * 128 + w + (r ^ k8);
}
__device__ __forceinline__ int b_word(int n, int k) {
    int t = (n & 7) * 4 + (k & 3);
    int r = (k & 7) >> 2;
    int k8 = k >> 3;
    int w = (t * 2) ^ (((t >> 2) & 7) << 1) ^ (k8 << 1);
    return (k8 * 16 + (n >> 3)) * 64 + w + r;
}

template<bool TN, int CMODE>
__device__ __forceinline__ void tf32_body(
    const float* __restrict__ A, const float* __restrict__ B, float* __restrict__ C,
    int K, int lda, int ldb, int ldc, int bm, int bn)
{
    __shared__ __align__(16) unsigned As[2][2048];
    __shared__ __align__(16) unsigned Bs[2][2048];
    if (CMODE == 2) {                    // S[t,l] = 0 for t < l  ->  start k at bm
        if (TN) { A += (long long)bm * lda; B += (long long)bm * ldb; }
        else    { A += bm; B += bm; }
        K -= bm;
    }
    const int tid = threadIdx.x;
    const int lane = tid & 31;
    const int wid = tid >> 5;
    const int wm = (wid & 3) * 2;    // m16-tile base index (0..7, step 2)
    const int wn = (wid >> 2) * 4;   // n8-tile base index (0..15, step 4)

    float acc[2][4][4];
#pragma unroll
    for (int x = 0; x < 2; ++x)
#pragma unroll
        for (int y = 0; y < 4; ++y)
#pragma unroll
            for (int z = 0; z < 4; ++z) acc[x][y][z] = 0.0f;

    // staging thread mapping: each thread loads exactly one float4 of A and B
    int r0, c0;
    if (!TN) { r0 = tid >> 2; c0 = (tid & 3) * 4; }   // r0 = m/n row 0..127, c0 = k
    else     { r0 = tid & 15; c0 = (tid >> 4) * 4; }  // r0 = k row 0..15, c0 = m/n 0..124

    const int ntl = K / 16;
    float4 a0, b0;

    if (!TN) {
        a0 = *(const float4*)(A + (long long)(bm + r0) * lda + c0);
        b0 = *(const float4*)(B + (long long)(bn + r0) * ldb + c0);
    } else {
        a0 = *(const float4*)(A + (long long)r0 * lda + bm + c0);
        b0 = *(const float4*)(B + (long long)r0 * ldb + bn + c0);
    }

    int buf = 0;
    {
        const float* av = (const float*)&a0;
        const float* bv = (const float*)&b0;
        if (!TN) {
#pragma unroll
            for (int j = 0; j < 4; ++j) {
                As[0][a_word(r0, c0 + j)] = f2tf(av[j]);
                Bs[0][b_word(r0, c0 + j)] = f2tf(bv[j]);
            }
        } else {
#pragma unroll
            for (int j = 0; j < 4; ++j) {
                As[0][a_word(c0 + j, r0)] = f2tf(av[j]);
                Bs[0][b_word(c0 + j, r0)] = f2tf(bv[j]);
            }
        }
    }
    __syncthreads();

    for (int it = 0; it < ntl; ++it) {
        if (it + 1 < ntl) {
            const int k0 = (it + 1) * 16;
            if (!TN) {
                a0 = *(const float4*)(A + (long long)(bm + r0) * lda + k0 + c0);
                b0 = *(const float4*)(B + (long long)(bn + r0) * ldb + k0 + c0);
            } else {
                a0 = *(const float4*)(A + (long long)(k0 + r0) * lda + bm + c0);
                b0 = *(const float4*)(B + (long long)(k0 + r0) * ldb + bn + c0);
            }
        }
        const unsigned* Asb = As[buf];
        const unsigned* Bsb = Bs[buf];
#pragma unroll
        for (int k8 = 0; k8 < 2; ++k8) {
            unsigned af[2][4];
            unsigned bfm[4][2];
#pragma unroll
            for (int mt = 0; mt < 2; ++mt) {
                uint4 w = *(const uint4*)&Asb[(k8 * 8 + wm + mt) * 128 +
                                              ((lane * 4) ^ (((lane >> 2) & 7) << 2))];
                af[mt][0] = k8 ? w.y : w.x;
                af[mt][1] = k8 ? w.x : w.y;
                af[mt][2] = k8 ? w.w : w.z;
                af[mt][3] = k8 ? w.z : w.w;
            }
#pragma unroll
            for (int nt = 0; nt < 4; ++nt) {
                uint2 w = *(const uint2*)&Bsb[(k8 * 16 + wn + nt) * 64 +
                                              ((lane * 2) ^ (((lane >> 2) & 7) << 1) ^ (k8 << 1))];
                bfm[nt][0] = w.x;
                bfm[nt][1] = w.y;
            }
#pragma unroll
            for (int mt = 0; mt < 2; ++mt)
#pragma unroll
                for (int nt = 0; nt < 4; ++nt)
                    mma8(acc[mt][nt], af[mt], bfm[nt]);
        }
        if (it + 1 < ntl) {
            buf ^= 1;
            const float* av = (const float*)&a0;
            const float* bv = (const float*)&b0;
            if (!TN) {
#pragma unroll
                for (int j = 0; j < 4; ++j) {
                    As[buf][a_word(r0, c0 + j)] = f2tf(av[j]);
                    Bs[buf][b_word(r0, c0 + j)] = f2tf(bv[j]);
                }
            } else {
#pragma unroll
                for (int j = 0; j < 4; ++j) {
                    As[buf][a_word(c0 + j, r0)] = f2tf(av[j]);
                    Bs[buf][b_word(c0 + j, r0)] = f2tf(bv[j]);
                }
            }
            __syncthreads();
        }
    }

    const int gid = lane >> 2;
    const int tig = lane & 3;
#pragma unroll
    for (int mt = 0; mt < 2; ++mt) {
        const long long row = bm + (wm + mt) * 16 + gid;
#pragma unroll
        for (int nt = 0; nt < 4; ++nt) {
            const int col = bn + (wn + nt) * 8 + tig * 2;
            *(float2*)(C + row * ldc + col) = make_float2(acc[mt][nt][0], acc[mt][nt][1]);
            *(float2*)(C + (row + 8) * ldc + col) = make_float2(acc[mt][nt][2], acc[mt][nt][3]);
        }
    }
}

// Generic strided-batch wrapper
template<bool TN, int CMODE>
__global__ __launch_bounds__(512) void gemm_tf32(
    const float* __restrict__ A, const float* __restrict__ B, float* __restrict__ C,
    int K, int lda, int ldb, int ldc,
    long long sA, long long sB, long long sC)
{
    const int bm = blockIdx.y * 128;
    const int bn = blockIdx.x * 128;
    if (CMODE == 1 && bn > bm) return;   // fully-masked tile: softmax writes zeros
    tf32_body<TN, CMODE>(A + (long long)blockIdx.z * sA,
                         B + (long long)blockIdx.z * sB,
                         C + (long long)blockIdx.z * sC,
                         K, lda, ldb, ldc, bm, bn);
}

// Down-projections merged: z=0 -> ckv, z=1 -> cq (pointer select only; all dims uniform)
__global__ __launch_bounds__(512) void gemm_down(
    const float* __restrict__ h, const float* __restrict__ w_dkv,
    const float* __restrict__ w_dq, float* __restrict__ ckv, float* __restrict__ cq)
{
    const float* B = w_dkv;
    float* C = ckv;
    if (blockIdx.z) { B = w_dq; C = cq; }
    tf32_body<false, 0>(h, B, C, D, D, D, DC, blockIdx.y * 128, blockIdx.x * 128);
}

// ============================================================
// 64x64 fp32 GEMM (N=64 cases: k_r, q_r) — FFMA2 mainloop
// ============================================================
#define SM_ 64
#define SK_ 16
__global__ __launch_bounds__(256) void gemm_nt64(
    const float* __restrict__ A, const float* __restrict__ B, float* __restrict__ C,
    int K, int lda, int ldb, int ldc,
    long long sA, long long sB, long long sC)
{
    __shared__ float As[SK_][SM_];
    __shared__ float Bs[SK_][SM_];
    A += (long long)blockIdx.z * sA;
    B += (long long)blockIdx.z * sB;
    C += (long long)blockIdx.z * sC;
    const int bm = blockIdx.y * SM_;
    const int bn = blockIdx.x * SM_;
    const int tid = threadIdx.x;
    const int tx = tid & 15;
    const int ty = tid >> 4;
    const int lrow = tid >> 2;
    const int lcol = (tid & 3) * 4;

    ull acc2[2][4] = {};

    for (int k0 = 0; k0 < K; k0 += SK_) {
        float4 a = *(const float4*)(A + (long long)(bm + lrow) * lda + k0 + lcol);
        float4 b = *(const float4*)(B + (long long)(bn + lrow) * ldb + k0 + lcol);
        __syncthreads();
        As[lcol + 0][lrow] = a.x; As[lcol + 1][lrow] = a.y;
        As[lcol + 2][lrow] = a.z; As[lcol + 3][lrow] = a.w;
        Bs[lcol + 0][lrow] = b.x; Bs[lcol + 1][lrow] = b.y;
        Bs[lcol + 2][lrow] = b.z; Bs[lcol + 3][lrow] = b.w;
        __syncthreads();
#pragma unroll
        for (int kk = 0; kk < SK_; ++kk) {
            float4 av = *(const float4*)(&As[kk][ty * 4]);
            float4 bv = *(const float4*)(&Bs[kk][tx * 4]);
            ull ap[2];
            ap[0] = ((const ull*)&av)[0];
            ap[1] = ((const ull*)&av)[1];
            ull bb[4];
            bb[0] = dup2(bv.x); bb[1] = dup2(bv.y);
            bb[2] = dup2(bv.z); bb[3] = dup2(bv.w);
#pragma unroll
            for (int p = 0; p < 2; ++p)
#pragma unroll
                for (int j = 0; j < 4; ++j)
                    ffma2(acc2[p][j], ap[p], bb[j]);
        }
    }

#pragma unroll
    for (int p = 0; p < 2; ++p) {
#pragma unroll
        for (int half = 0; half < 2; ++half) {
            const int crow = bm + ty * 4 + p * 2 + half;
            F2u v0, v1, v2, v3;
            v0.u = acc2[p][0]; v1.u = acc2[p][1];
            v2.u = acc2[p][2]; v3.u = acc2[p][3];
            float4 o = half ? make_float4(v0.f.y, v1.f.y, v2.f.y, v3.f.y)
                            : make_float4(v0.f.x, v1.f.x, v2.f.x, v3.f.x);
            *(float4*)(C + (long long)crow * ldc + bn + tx * 4) = o;
        }
    }
}

// ============================================================
// Elementwise kernels
// ============================================================
__global__ void rope_q_kernel(float* __restrict__ q, const float* __restrict__ freqs)
{
    int idx = blockIdx.x * blockDim.x + threadIdx.x;   // NH*T*32
    int i = idx & 31;
    int t = (idx >> 5) & (T - 1);
    int n = idx >> 16;
    float ang = freqs[t * (DRH / 2) + i];
    float c, s;
    __sincosf(ang, &s, &c);
    float* base = q + ((size_t)(n * T + t)) * QKD + DH;
    float re = base[i], im = base[i + 32];
    base[i]      = re * c - im * s;
    base[i + 32] = re * s + im * c;
}

__global__ void rope_k_bcast_kernel(const float* __restrict__ kr, float* __restrict__ kbuf,
                                    const float* __restrict__ freqs)
{
    int idx = blockIdx.x * blockDim.x + threadIdx.x;   // T*32
    int i = idx & 31;
    int t = idx >> 5;
    float ang = freqs[t * (DRH / 2) + i];
    float c, s;
    __sincosf(ang, &s, &c);
    float re = kr[t * DRH + i], im = kr[t * DRH + 32 + i];
    const float inv_nh = 1.0f / (float)NH;
    float rr = (re * c - im * s) * inv_nh;
    float ri = (re * s + im * c) * inv_nh;
#pragma unroll
    for (int n = 0; n < NH; ++n) {
        float* b = kbuf + ((size_t)(n * T + t)) * QKD + DH;
        b[i]      = rr;
        b[i + 32] = ri;
    }
}

__global__ void wo_transpose_kernel(const float* __restrict__ wo, float* __restrict__ wt)
{
    int idx = blockIdx.x * blockDim.x + threadIdx.x;   // D * NH * DH
    int j = idx & (NH * DH - 1);
    int d = idx >> 11;
    int n = j >> 7;
    int e = j & (DH - 1);
    wt[idx] = wo[(size_t)d * (DH * NH) + e * NH + n];
}

// Causal softmax: row t over l, analytic mask (l<=t valid), zeros elsewhere.
__global__ __launch_bounds__(256) void softmax_kernel(
    float* __restrict__ logits, float scale)
{
    const int t = blockIdx.x;
    const int n = blockIdx.y;
    float* __restrict__ row = logits + ((size_t)n * T + t) * T;
    const int tid = threadIdx.x;
    const int wbase = tid & ~31;

    float v[8];
    float mx = -1e30f;
#pragma unroll
    for (int j = 0; j < 8; ++j) {
        const int l = tid + j * 256;
        if (wbase + j * 256 > t) {           // whole warp-chunk masked: skip load
            v[j] = -1e30f;
        } else {
            float x = row[l];
            v[j] = (l <= t) ? x * scale : -1e30f;
        }
        mx = fmaxf(mx, v[j]);
    }
    __shared__ float redm[8], reds[8];
#pragma unroll
    for (int o = 16; o; o >>= 1) mx = fmaxf(mx, __shfl_xor_sync(0xffffffffu, mx, o));
    if ((tid & 31) == 0) redm[tid >> 5] = mx;
    __syncthreads();
    mx = redm[0];
#pragma unroll
    for (int w = 1; w < 8; ++w) mx = fmaxf(mx, redm[w]);

    float sum = 0.0f;
#pragma unroll
    for (int j = 0; j < 8; ++j) {
        if (v[j] > -1e29f) {
            v[j] = __expf(v[j] - mx);
            sum += v[j];
        } else {
            v[j] = 0.0f;
        }
    }
#pragma unroll
    for (int o = 16; o; o >>= 1) sum += __shfl_xor_sync(0xffffffffu, sum, o);
    if ((tid & 31) == 0) reds[tid >> 5] = sum;
    __syncthreads();
    sum = reds[0];
#pragma unroll
    for (int w = 1; w < 8; ++w) sum += reds[w];

    float inv = 1.0f / sum;
#pragma unroll
    for (int j = 0; j < 8; ++j)
        row[tid + j * 256] = v[j] * inv;
}

// ============================================================
// Launch
// ============================================================
extern "C" void kernel_launch(void* const* d_in, const int* in_sizes, int n_in,
                              void* d_out, int out_size)
{
    const float* h     = (const float*)d_in[0];
    const float* freqs = (const float*)d_in[1];
    const float* w_dkv = (const float*)d_in[3];
    const float* w_uk  = (const float*)d_in[4];
    const float* w_uv  = (const float*)d_in[5];
    const float* w_dq  = (const float*)d_in[6];
    const float* w_uq  = (const float*)d_in[7];
    const float* w_qr  = (const float*)d_in[8];
    const float* w_kr  = (const float*)d_in[9];
    const float* w_o   = (const float*)d_in[10];
    float* out = (float*)d_out;
    (void)in_sizes; (void)n_in; (void)out_size;

    float *ckv, *cq, *q, *k, *v, *kr, *logits, *attn, *wot;
    cudaGetSymbolAddress((void**)&ckv,    g_ckv);
    cudaGetSymbolAddress((void**)&cq,     g_cq);
    cudaGetSymbolAddress((void**)&q,      g_q);
    cudaGetSymbolAddress((void**)&k,      g_k);
    cudaGetSymbolAddress((void**)&v,      g_v);
    cudaGetSymbolAddress((void**)&kr,     g_kr);
    cudaGetSymbolAddress((void**)&logits, g_logits);
    cudaGetSymbolAddress((void**)&attn,   g_attn);
    cudaGetSymbolAddress((void**)&wot,    g_wot);

    const dim3 blk(512);
    const long long sQ = (long long)T * QKD;

    // Latents: c_kv + c_q in ONE launch (z selects; all dims uniform)
    gemm_down<<<dim3(DC / 128, T / 128, 2), blk>>>(h, w_dkv, w_dq, ckv, cq);
    // k_r (pre-rope): N=64, fp32
    gemm_nt64<<<dim3(1, T / SM_, 1), 256>>>(h, w_kr, kr, D, D, D, DRH, 0, 0, 0);

    // Per-head up-projections
    gemm_tf32<false, 0><<<dim3(1, T / 128, NH), blk>>>(ckv, w_uk, k, DC, DC, NH * DC, QKD, 0, DC, sQ);
    gemm_tf32<false, 0><<<dim3(1, T / 128, NH), blk>>>(ckv, w_uv, v, DC, DC, NH * DC, DH,  0, DC, (long long)T * DH);
    gemm_tf32<false, 0><<<dim3(1, T / 128, NH), blk>>>(cq,  w_uq, q, DC, DC, NH * DC, QKD, 0, DC, sQ);
    // q_r: N=64, fp32
    gemm_nt64<<<dim3(1, T / SM_, NH), 256>>>(cq, w_qr, q + DH, DC, DC, NH * DC, QKD, 0, DC, sQ);

    // Rope
    rope_q_kernel<<<(NH * T * 32) / 256, 256>>>(q, freqs);
    rope_k_bcast_kernel<<<(T * 32) / 256, 256>>>(kr, k, freqs);

    // logits[n,t,l] = q . k  — skip fully-masked upper tiles
    gemm_tf32<false, 1><<<dim3(T / 128, T / 128, NH), blk>>>(q, k, logits, QKD, QKD, QKD, T, sQ, sQ, (long long)T * T);

    // causal softmax, scale = 1/sqrt(192); writes exact zeros for l > t
    softmax_kernel<<<dim3(T, NH), 256>>>(logits, 0.07216878364870323f);

    // out[n,l,e] = sum_{t>=l} S[n,t,l] v[n,t,e]  — k-loop starts at bm
    gemm_tf32<true, 2><<<dim3(1, T / 128, NH), blk>>>(logits, v, attn, T, T, DH, NH * DH,
                                                      (long long)T * T, (long long)T * DH, DH);

    // w_o permute then final projection
    wo_transpose_kernel<<<(D * NH * DH) / 256, 256>>>(w_o, wot);
    gemm_tf32<false, 0><<<dim3(D / 128, T / 128, 1), blk>>>(attn, wot, out, NH * DH, NH * DH, NH * DH, D, 0, 0, 0);
}

// round 13
// speedup vs baseline: 1.5288x; 1.1109x over previous
#include <cuda_runtime.h>
#include <cuda_bf16.h>

// Problem constants
#define T   2048
#define D   2048
#define NH  16
#define DH  128
#define DRH 64
#define DC  512
#define QKD 192   // DH + DRH

// -------- scratch (device globals; no allocation allowed) --------
__device__ float g_ckv[(size_t)T * DC];
__device__ float g_cq [(size_t)T * DC];
__device__ float g_q  [(size_t)NH * T * QKD];
__device__ float g_k  [(size_t)NH * T * QKD];
__device__ float g_v  [(size_t)NH * T * DH];
__device__ float g_kr [(size_t)T * DRH];
__device__ float g_logits[(size_t)NH * T * T];
__device__ float g_attn[(size_t)T * NH * DH];
__device__ float g_wot [(size_t)D * NH * DH];

typedef unsigned long long ull;

__device__ __forceinline__ void ffma2(ull& d, ull a, ull b) {
    asm("fma.rn.f32x2 %0, %1, %2, %0;" : "+l"(d) : "l"(a), "l"(b));
}
__device__ __forceinline__ ull dup2(float x) {
    ull r;
    asm("mov.b64 %0, {%1, %1};" : "=l"(r) : "f"(x));
    return r;
}
union F2u { ull u; float2 f; };

__device__ __forceinline__ unsigned f2tf(float x) {
    unsigned r;
    asm("cvt.rna.tf32.f32 %0, %1;" : "=r"(r) : "f"(x));
    return r;
}

__device__ __forceinline__ void mma8(float* c, const unsigned* a, const unsigned* b) {
    asm("mma.sync.aligned.m16n8k8.row.col.f32.tf32.tf32.f32 "
        "{%0,%1,%2,%3}, {%4,%5,%6,%7}, {%8,%9}, {%0,%1,%2,%3};"
        : "+f"(c[0]), "+f"(c[1]), "+f"(c[2]), "+f"(c[3])
        : "r"(a[0]), "r"(a[1]), "r"(a[2]), "r"(a[3]), "r"(b[0]), "r"(b[1]));
}

// ============================================================
// TF32 mma.sync GEMM: 128x128 tile, BK=8, 256 threads (8 warps),
// warp tile 64x32 (4 m16-tiles x 4 n8-tiles), 2 CTAs/SM.
// Fragment-major swizzled smem (k8=0 slice of the validated R8 layout).
// CMODE: 0 = plain, 1 = skip upper-triangular tiles (causal logits),
//        2 = start k-loop at bm (causal S^T V).
// ============================================================

// smem word index for A value (m in [0,128), k in [0,8))
__device__ __forceinline__ int a_word8(int m, int k) {
    int t = (m & 7) * 4 + (k & 3);
    int r = ((k >> 2) << 1) | ((m >> 3) & 1);
    int w = (t * 4) ^ (((t >> 2) & 7) << 2);
    return (m >> 4) * 128 + w + r;
}
// smem word index for B value (n in [0,128), k in [0,8))
__device__ __forceinline__ int b_word8(int n, int k) {
    int t = (n & 7) * 4 + (k & 3);
    int r = k >> 2;
    int w = (t * 2) ^ (((t >> 2) & 7) << 1);
    return (n >> 3) * 64 + w + r;
}

template<bool TN, int CMODE>
__device__ __forceinline__ void tf32_body(
    const float* __restrict__ A, const float* __restrict__ B, float* __restrict__ C,
    int K, int lda, int ldb, int ldc, int bm, int bn)
{
    __shared__ __align__(16) unsigned As[2][1024];
    __shared__ __align__(16) unsigned Bs[2][1024];
    if (CMODE == 2) {                    // S[t,l] = 0 for t < l  ->  start k at bm
        if (TN) { A += (long long)bm * lda; B += (long long)bm * ldb; }
        else    { A += bm; B += bm; }
        K -= bm;
    }
    const int tid = threadIdx.x;
    const int lane = tid & 31;
    const int wid = tid >> 5;
    const int wm = (wid & 1) * 4;    // m16-tile base (0 or 4)
    const int wn = (wid >> 1) * 4;   // n8-tile base (0,4,8,12)

    float acc[4][4][4];
#pragma unroll
    for (int x = 0; x < 4; ++x)
#pragma unroll
        for (int y = 0; y < 4; ++y)
#pragma unroll
            for (int z = 0; z < 4; ++z) acc[x][y][z] = 0.0f;

    // staging: each thread loads exactly one float4 of A and one of B per tile
    int r0, c0;
    if (!TN) { r0 = tid >> 1; c0 = (tid & 1) * 4; }   // r0 = m/n row 0..127, c0 = k {0,4}
    else     { r0 = tid & 7;  c0 = (tid >> 3) * 4; }  // r0 = k row 0..7, c0 = m/n 0..124

    const int ntl = K / 8;
    float4 a0, b0;

    if (!TN) {
        a0 = *(const float4*)(A + (long long)(bm + r0) * lda + c0);
        b0 = *(const float4*)(B + (long long)(bn + r0) * ldb + c0);
    } else {
        a0 = *(const float4*)(A + (long long)r0 * lda + bm + c0);
        b0 = *(const float4*)(B + (long long)r0 * ldb + bn + c0);
    }

    int buf = 0;
    {
        const float* av = (const float*)&a0;
        const float* bv = (const float*)&b0;
        if (!TN) {
#pragma unroll
            for (int j = 0; j < 4; ++j) {
                As[0][a_word8(r0, c0 + j)] = f2tf(av[j]);
                Bs[0][b_word8(r0, c0 + j)] = f2tf(bv[j]);
            }
        } else {
#pragma unroll
            for (int j = 0; j < 4; ++j) {
                As[0][a_word8(c0 + j, r0)] = f2tf(av[j]);
                Bs[0][b_word8(c0 + j, r0)] = f2tf(bv[j]);
            }
        }
    }
    __syncthreads();

    for (int it = 0; it < ntl; ++it) {
        if (it + 1 < ntl) {
            const int k0 = (it + 1) * 8;
            if (!TN) {
                a0 = *(const float4*)(A + (long long)(bm + r0) * lda + k0 + c0);
                b0 = *(const float4*)(B + (long long)(bn + r0) * ldb + k0 + c0);
            } else {
                a0 = *(const float4*)(A + (long long)(k0 + r0) * lda + bm + c0);
                b0 = *(const float4*)(B + (long long)(k0 + r0) * ldb + bn + c0);
            }
        }
        const unsigned* Asb = As[buf];
        const unsigned* Bsb = Bs[buf];
        {
            unsigned af[4][4];
            unsigned bfm[4][2];
            const int aoff = (lane * 4) ^ (((lane >> 2) & 7) << 2);
            const int boff = (lane * 2) ^ (((lane >> 2) & 7) << 1);
#pragma unroll
            for (int mt = 0; mt < 4; ++mt) {
                uint4 w = *(const uint4*)&Asb[(wm + mt) * 128 + aoff];
                af[mt][0] = w.x; af[mt][1] = w.y; af[mt][2] = w.z; af[mt][3] = w.w;
            }
#pragma unroll
            for (int nt = 0; nt < 4; ++nt) {
                uint2 w = *(const uint2*)&Bsb[(wn + nt) * 64 + boff];
                bfm[nt][0] = w.x;
                bfm[nt][1] = w.y;
            }
#pragma unroll
            for (int mt = 0; mt < 4; ++mt)
#pragma unroll
                for (int nt = 0; nt < 4; ++nt)
                    mma8(acc[mt][nt], af[mt], bfm[nt]);
        }
        if (it + 1 < ntl) {
            buf ^= 1;
            const float* av = (const float*)&a0;
            const float* bv = (const float*)&b0;
            if (!TN) {
#pragma unroll
                for (int j = 0; j < 4; ++j) {
                    As[buf][a_word8(r0, c0 + j)] = f2tf(av[j]);
                    Bs[buf][b_word8(r0, c0 + j)] = f2tf(bv[j]);
                }
            } else {
#pragma unroll
                for (int j = 0; j < 4; ++j) {
                    As[buf][a_word8(c0 + j, r0)] = f2tf(av[j]);
                    Bs[buf][b_word8(c0 + j, r0)] = f2tf(bv[j]);
                }
            }
            __syncthreads();
        }
    }

    const int gid = lane >> 2;
    const int tig = lane & 3;
#pragma unroll
    for (int mt = 0; mt < 4; ++mt) {
        const long long row = bm + (wm + mt) * 16 + gid;
#pragma unroll
        for (int nt = 0; nt < 4; ++nt) {
            const int col = bn + (wn + nt) * 8 + tig * 2;
            *(float2*)(C + row * ldc + col) = make_float2(acc[mt][nt][0], acc[mt][nt][1]);
            *(float2*)(C + (row + 8) * ldc + col) = make_float2(acc[mt][nt][2], acc[mt][nt][3]);
        }
    }
}

// Generic strided-batch wrapper
template<bool TN, int CMODE>
__global__ __launch_bounds__(256, 2) void gemm_tf32(
    const float* __restrict__ A, const float* __restrict__ B, float* __restrict__ C,
    int K, int lda, int ldb, int ldc,
    long long sA, long long sB, long long sC)
{
    const int bm = blockIdx.y * 128;
    const int bn = blockIdx.x * 128;
    if (CMODE == 1 && bn > bm) return;   // fully-masked tile: softmax writes zeros
    tf32_body<TN, CMODE>(A + (long long)blockIdx.z * sA,
                         B + (long long)blockIdx.z * sB,
                         C + (long long)blockIdx.z * sC,
                         K, lda, ldb, ldc, bm, bn);
}

// Down-projections merged: z=0 -> ckv, z=1 -> cq (pointer select only)
__global__ __launch_bounds__(256, 2) void gemm_down(
    const float* __restrict__ h, const float* __restrict__ w_dkv,
    const float* __restrict__ w_dq, float* __restrict__ ckv, float* __restrict__ cq)
{
    const float* B = w_dkv;
    float* C = ckv;
    if (blockIdx.z) { B = w_dq; C = cq; }
    tf32_body<false, 0>(h, B, C, D, D, D, DC, blockIdx.y * 128, blockIdx.x * 128);
}

// ============================================================
// 64x64 fp32 GEMM (N=64 cases: k_r, q_r) — FFMA2 mainloop
// ============================================================
#define SM_ 64
#define SK_ 16
__global__ __launch_bounds__(256) void gemm_nt64(
    const float* __restrict__ A, const float* __restrict__ B, float* __restrict__ C,
    int K, int lda, int ldb, int ldc,
    long long sA, long long sB, long long sC)
{
    __shared__ float As[SK_][SM_];
    __shared__ float Bs[SK_][SM_];
    A += (long long)blockIdx.z * sA;
    B += (long long)blockIdx.z * sB;
    C += (long long)blockIdx.z * sC;
    const int bm = blockIdx.y * SM_;
    const int bn = blockIdx.x * SM_;
    const int tid = threadIdx.x;
    const int tx = tid & 15;
    const int ty = tid >> 4;
    const int lrow = tid >> 2;
    const int lcol = (tid & 3) * 4;

    ull acc2[2][4] = {};

    for (int k0 = 0; k0 < K; k0 += SK_) {
        float4 a = *(const float4*)(A + (long long)(bm + lrow) * lda + k0 + lcol);
        float4 b = *(const float4*)(B + (long long)(bn + lrow) * ldb + k0 + lcol);
        __syncthreads();
        As[lcol + 0][lrow] = a.x; As[lcol + 1][lrow] = a.y;
        As[lcol + 2][lrow] = a.z; As[lcol + 3][lrow] = a.w;
        Bs[lcol + 0][lrow] = b.x; Bs[lcol + 1][lrow] = b.y;
        Bs[lcol + 2][lrow] = b.z; Bs[lcol + 3][lrow] = b.w;
        __syncthreads();
#pragma unroll
        for (int kk = 0; kk < SK_; ++kk) {
            float4 av = *(const float4*)(&As[kk][ty * 4]);
            float4 bv = *(const float4*)(&Bs[kk][tx * 4]);
            ull ap[2];
            ap[0] = ((const ull*)&av)[0];
            ap[1] = ((const ull*)&av)[1];
            ull bb[4];
            bb[0] = dup2(bv.x); bb[1] = dup2(bv.y);
            bb[2] = dup2(bv.z); bb[3] = dup2(bv.w);
#pragma unroll
            for (int p = 0; p < 2; ++p)
#pragma unroll
                for (int j = 0; j < 4; ++j)
                    ffma2(acc2[p][j], ap[p], bb[j]);
        }
    }

#pragma unroll
    for (int p = 0; p < 2; ++p) {
#pragma unroll
        for (int half = 0; half < 2; ++half) {
            const int crow = bm + ty * 4 + p * 2 + half;
            F2u v0, v1, v2, v3;
            v0.u = acc2[p][0]; v1.u = acc2[p][1];
            v2.u = acc2[p][2]; v3.u = acc2[p][3];
            float4 o = half ? make_float4(v0.f.y, v1.f.y, v2.f.y, v3.f.y)
                            : make_float4(v0.f.x, v1.f.x, v2.f.x, v3.f.x);
            *(float4*)(C + (long long)crow * ldc + bn + tx * 4) = o;
        }
    }
}

// ============================================================
// Elementwise kernels
// ============================================================
__global__ void rope_q_kernel(float* __restrict__ q, const float* __restrict__ freqs)
{
    int idx = blockIdx.x * blockDim.x + threadIdx.x;   // NH*T*32
    int i = idx & 31;
    int t = (idx >> 5) & (T - 1);
    int n = idx >> 16;
    float ang = freqs[t * (DRH / 2) + i];
    float c, s;
    __sincosf(ang, &s, &c);
    float* base = q + ((size_t)(n * T + t)) * QKD + DH;
    float re = base[i], im = base[i + 32];
    base[i]      = re * c - im * s;
    base[i + 32] = re * s + im * c;
}

__global__ void rope_k_bcast_kernel(const float* __restrict__ kr, float* __restrict__ kbuf,
                                    const float* __restrict__ freqs)
{
    int idx = blockIdx.x * blockDim.x + threadIdx.x;   // T*32
    int i = idx & 31;
    int t = idx >> 5;
    float ang = freqs[t * (DRH / 2) + i];
    float c, s;
    __sincosf(ang, &s, &c);
    float re = kr[t * DRH + i], im = kr[t * DRH + 32 + i];
    const float inv_nh = 1.0f / (float)NH;
    float rr = (re * c - im * s) * inv_nh;
    float ri = (re * s + im * c) * inv_nh;
#pragma unroll
    for (int n = 0; n < NH; ++n) {
        float* b = kbuf + ((size_t)(n * T + t)) * QKD + DH;
        b[i]      = rr;
        b[i + 32] = ri;
    }
}

__global__ void wo_transpose_kernel(const float* __restrict__ wo, float* __restrict__ wt)
{
    int idx = blockIdx.x * blockDim.x + threadIdx.x;   // D * NH * DH
    int j = idx & (NH * DH - 1);
    int d = idx >> 11;
    int n = j >> 7;
    int e = j & (DH - 1);
    wt[idx] = wo[(size_t)d * (DH * NH) + e * NH + n];
}

// Causal softmax: row t over l, analytic mask (l<=t valid), zeros elsewhere.
__global__ __launch_bounds__(256) void softmax_kernel(
    float* __restrict__ logits, float scale)
{
    const int t = blockIdx.x;
    const int n = blockIdx.y;
    float* __restrict__ row = logits + ((size_t)n * T + t) * T;
    const int tid = threadIdx.x;
    const int wbase = tid & ~31;

    float v[8];
    float mx = -1e30f;
#pragma unroll
    for (int j = 0; j < 8; ++j) {
        const int l = tid + j * 256;
        if (wbase + j * 256 > t) {
            v[j] = -1e30f;
        } else {
            float x = row[l];
            v[j] = (l <= t) ? x * scale : -1e30f;
        }
        mx = fmaxf(mx, v[j]);
    }
    __shared__ float redm[8], reds[8];
#pragma unroll
    for (int o = 16; o; o >>= 1) mx = fmaxf(mx, __shfl_xor_sync(0xffffffffu, mx, o));
    if ((tid & 31) == 0) redm[tid >> 5] = mx;
    __syncthreads();
    mx = redm[0];
#pragma unroll
    for (int w = 1; w < 8; ++w) mx = fmaxf(mx, redm[w]);

    float sum = 0.0f;
#pragma unroll
    for (int j = 0; j < 8; ++j) {
        if (v[j] > -1e29f) {
            v[j] = __expf(v[j] - mx);
            sum += v[j];
        } else {
            v[j] = 0.0f;
        }
    }
#pragma unroll
    for (int o = 16; o; o >>= 1) sum += __shfl_xor_sync(0xffffffffu, sum, o);
    if ((tid & 31) == 0) reds[tid >> 5] = sum;
    __syncthreads();
    sum = reds[0];
#pragma unroll
    for (int w = 1; w < 8; ++w) sum += reds[w];

    float inv = 1.0f / sum;
#pragma unroll
    for (int j = 0; j < 8; ++j)
        row[tid + j * 256] = v[j] * inv;
}

// ============================================================
// Launch
// ============================================================
extern "C" void kernel_launch(void* const* d_in, const int* in_sizes, int n_in,
                              void* d_out, int out_size)
{
    const float* h     = (const float*)d_in[0];
    const float* freqs = (const float*)d_in[1];
    const float* w_dkv = (const float*)d_in[3];
    const float* w_uk  = (const float*)d_in[4];
    const float* w_uv  = (const float*)d_in[5];
    const float* w_dq  = (const float*)d_in[6];
    const float* w_uq  = (const float*)d_in[7];
    const float* w_qr  = (const float*)d_in[8];
    const float* w_kr  = (const float*)d_in[9];
    const float* w_o   = (const float*)d_in[10];
    float* out = (float*)d_out;
    (void)in_sizes; (void)n_in; (void)out_size;

    float *ckv, *cq, *q, *k, *v, *kr, *logits, *attn, *wot;
    cudaGetSymbolAddress((void**)&ckv,    g_ckv);
    cudaGetSymbolAddress((void**)&cq,     g_cq);
    cudaGetSymbolAddress((void**)&q,      g_q);
    cudaGetSymbolAddress((void**)&k,      g_k);
    cudaGetSymbolAddress((void**)&v,      g_v);
    cudaGetSymbolAddress((void**)&kr,     g_kr);
    cudaGetSymbolAddress((void**)&logits, g_logits);
    cudaGetSymbolAddress((void**)&attn,   g_attn);
    cudaGetSymbolAddress((void**)&wot,    g_wot);

    const dim3 blk(256);
    const long long sQ = (long long)T * QKD;

    // Latents: c_kv + c_q in ONE launch (z selects; uniform dims)
    gemm_down<<<dim3(DC / 128, T / 128, 2), blk>>>(h, w_dkv, w_dq, ckv, cq);
    // k_r (pre-rope): N=64, fp32
    gemm_nt64<<<dim3(1, T / SM_, 1), 256>>>(h, w_kr, kr, D, D, D, DRH, 0, 0, 0);

    // Per-head up-projections
    gemm_tf32<false, 0><<<dim3(1, T / 128, NH), blk>>>(ckv, w_uk, k, DC, DC, NH * DC, QKD, 0, DC, sQ);
    gemm_tf32<false, 0><<<dim3(1, T / 128, NH), blk>>>(ckv, w_uv, v, DC, DC, NH * DC, DH,  0, DC, (long long)T * DH);
    gemm_tf32<false, 0><<<dim3(1, T / 128, NH), blk>>>(cq,  w_uq, q, DC, DC, NH * DC, QKD, 0, DC, sQ);
    // q_r: N=64, fp32
    gemm_nt64<<<dim3(1, T / SM_, NH), 256>>>(cq, w_qr, q + DH, DC, DC, NH * DC, QKD, 0, DC, sQ);

    // Rope
    rope_q_kernel<<<(NH * T * 32) / 256, 256>>>(q, freqs);
    rope_k_bcast_kernel<<<(T * 32) / 256, 256>>>(kr, k, freqs);

    // logits[n,t,l] = q . k  — skip fully-masked upper tiles
    gemm_tf32<false, 1><<<dim3(T / 128, T / 128, NH), blk>>>(q, k, logits, QKD, QKD, QKD, T, sQ, sQ, (long long)T * T);

    // causal softmax, scale = 1/sqrt(192); writes exact zeros for l > t
    softmax_kernel<<<dim3(T, NH), 256>>>(logits, 0.07216878364870323f);

    // out[n,l,e] = sum_{t>=l} S[n,t,l] v[n,t,e]  — k-loop starts at bm
    gemm_tf32<true, 2><<<dim3(1, T / 128, NH), blk>>>(logits, v, attn, T, T, DH, NH * DH,
                                                      (long long)T * T, (long long)T * DH, DH);

    // w_o permute then final projection
    wo_transpose_kernel<<<(D * NH * DH) / 256, 256>>>(w_o, wot);
    gemm_tf32<false, 0><<<dim3(D / 128, T / 128, 1), blk>>>(attn, wot, out, NH * DH, NH * DH, NH * DH, D, 0, 0, 0);
}

// round 15
// speedup vs baseline: 1.7652x; 1.1546x over previous
#include <cuda_runtime.h>
#include <cuda_bf16.h>

// Problem constants
#define T   2048
#define D   2048
#define NH  16
#define DH  128
#define DRH 64
#define DC  512
#define QKD 192   // DH + DRH

// -------- scratch (device globals; no allocation allowed) --------
__device__ float g_ckv[(size_t)T * DC];
__device__ float g_cq [(size_t)T * DC];
__device__ float g_q  [(size_t)NH * T * QKD];
__device__ float g_k  [(size_t)NH * T * QKD];
__device__ float g_v  [(size_t)NH * T * DH];
__device__ float g_kr [(size_t)T * DRH];
__device__ float g_logits[(size_t)NH * T * T];
__device__ float g_attn[(size_t)T * NH * DH];
__device__ float g_wot [(size_t)D * NH * DH];

typedef unsigned long long ull;

__device__ __forceinline__ void ffma2(ull& d, ull a, ull b) {
    asm("fma.rn.f32x2 %0, %1, %2, %0;" : "+l"(d) : "l"(a), "l"(b));
}
__device__ __forceinline__ ull dup2(float x) {
    ull r;
    asm("mov.b64 %0, {%1, %1};" : "=l"(r) : "f"(x));
    return r;
}
union F2u { ull u; float2 f; };

__device__ __forceinline__ unsigned f2tf(float x) {
    unsigned r;
    asm("cvt.rna.tf32.f32 %0, %1;" : "=r"(r) : "f"(x));
    return r;
}

__device__ __forceinline__ void mma8(float* c, const unsigned* a, const unsigned* b) {
    asm("mma.sync.aligned.m16n8k8.row.col.f32.tf32.tf32.f32 "
        "{%0,%1,%2,%3}, {%4,%5,%6,%7}, {%8,%9}, {%0,%1,%2,%3};"
        : "+f"(c[0]), "+f"(c[1]), "+f"(c[2]), "+f"(c[3])
        : "r"(a[0]), "r"(a[1]), "r"(a[2]), "r"(a[3]), "r"(b[0]), "r"(b[1]));
}

// ============================================================
// TF32 mma.sync GEMM: 128x128 tile, BK=8, 256 threads (8 warps),
// warp tile 64x32, 2 CTAs/SM. RED=true: atomicAdd epilogue (split-K).
// ============================================================

// smem word index for A value (m in [0,128), k in [0,8))
__device__ __forceinline__ int a_word8(int m, int k) {
    int t = (m & 7) * 4 + (k & 3);
    int r = ((k >> 2) << 1) | ((m >> 3) & 1);
    int w = (t * 4) ^ (((t >> 2) & 7) << 2);
    return (m >> 4) * 128 + w + r;
}
// smem word index for B value (n in [0,128), k in [0,8))
__device__ __forceinline__ int b_word8(int n, int k) {
    int t = (n & 7) * 4 + (k & 3);
    int r = k >> 2;
    int w = (t * 2) ^ (((t >> 2) & 7) << 1);
    return (n >> 3) * 64 + w + r;
}

template<bool TN, bool RED>
__device__ __forceinline__ void tf32_body(
    const float* __restrict__ A, const float* __restrict__ B, float* __restrict__ C,
    int kbeg, int kend, int lda, int ldb, int ldc, int bm, int bn)
{
    __shared__ __align__(16) unsigned As[2][1024];
    __shared__ __align__(16) unsigned Bs[2][1024];
    if (TN) { A += (long long)kbeg * lda; B += (long long)kbeg * ldb; }
    else    { A += kbeg; B += kbeg; }
    const int K = kend - kbeg;

    const int tid = threadIdx.x;
    const int lane = tid & 31;
    const int wid = tid >> 5;
    const int wm = (wid & 1) * 4;    // m16-tile base (0 or 4)
    const int wn = (wid >> 1) * 4;   // n8-tile base (0,4,8,12)

    float acc[4][4][4];
#pragma unroll
    for (int x = 0; x < 4; ++x)
#pragma unroll
        for (int y = 0; y < 4; ++y)
#pragma unroll
            for (int z = 0; z < 4; ++z) acc[x][y][z] = 0.0f;

    // staging: one float4 of A and one of B per thread per tile.
    // NT: r0 = m/n row, c0 = k offset. TN: one warp per k-row, contiguous 512B row.
    int r0, c0;
    if (!TN) { r0 = tid >> 1; c0 = (tid & 1) * 4; }
    else     { r0 = tid >> 5; c0 = (tid & 31) * 4; }

    const int ntl = K / 8;
    float4 a0, b0;

    if (!TN) {
        a0 = *(const float4*)(A + (long long)(bm + r0) * lda + c0);
        b0 = *(const float4*)(B + (long long)(bn + r0) * ldb + c0);
    } else {
        a0 = *(const float4*)(A + (long long)r0 * lda + bm + c0);
        b0 = *(const float4*)(B + (long long)r0 * ldb + bn + c0);
    }

    int buf = 0;
    {
        const float* av = (const float*)&a0;
        const float* bv = (const float*)&b0;
        if (!TN) {
#pragma unroll
            for (int j = 0; j < 4; ++j) {
                As[0][a_word8(r0, c0 + j)] = f2tf(av[j]);
                Bs[0][b_word8(r0, c0 + j)] = f2tf(bv[j]);
            }
        } else {
#pragma unroll
            for (int j = 0; j < 4; ++j) {
                As[0][a_word8(c0 + j, r0)] = f2tf(av[j]);
                Bs[0][b_word8(c0 + j, r0)] = f2tf(bv[j]);
            }
        }
    }
    __syncthreads();

    for (int it = 0; it < ntl; ++it) {
        if (it + 1 < ntl) {
            const int k0 = (it + 1) * 8;
            if (!TN) {
                a0 = *(const float4*)(A + (long long)(bm + r0) * lda + k0 + c0);
                b0 = *(const float4*)(B + (long long)(bn + r0) * ldb + k0 + c0);
            } else {
                a0 = *(const float4*)(A + (long long)(k0 + r0) * lda + bm + c0);
                b0 = *(const float4*)(B + (long long)(k0 + r0) * ldb + bn + c0);
            }
        }
        const unsigned* Asb = As[buf];
        const unsigned* Bsb = Bs[buf];
        {
            unsigned af[4][4];
            unsigned bfm[4][2];
            const int aoff = (lane * 4) ^ (((lane >> 2) & 7) << 2);
            const int boff = (lane * 2) ^ (((lane >> 2) & 7) << 1);
#pragma unroll
            for (int mt = 0; mt < 4; ++mt) {
                uint4 w = *(const uint4*)&Asb[(wm + mt) * 128 + aoff];
                af[mt][0] = w.x; af[mt][1] = w.y; af[mt][2] = w.z; af[mt][3] = w.w;
            }
#pragma unroll
            for (int nt = 0; nt < 4; ++nt) {
                uint2 w = *(const uint2*)&Bsb[(wn + nt) * 64 + boff];
                bfm[nt][0] = w.x;
                bfm[nt][1] = w.y;
            }
#pragma unroll
            for (int mt = 0; mt < 4; ++mt)
#pragma unroll
                for (int nt = 0; nt < 4; ++nt)
                    mma8(acc[mt][nt], af[mt], bfm[nt]);
        }
        if (it + 1 < ntl) {
            buf ^= 1;
            const float* av = (const float*)&a0;
            const float* bv = (const float*)&b0;
            if (!TN) {
#pragma unroll
                for (int j = 0; j < 4; ++j) {
                    As[buf][a_word8(r0, c0 + j)] = f2tf(av[j]);
                    Bs[buf][b_word8(r0, c0 + j)] = f2tf(bv[j]);
                }
            } else {
#pragma unroll
                for (int j = 0; j < 4; ++j) {
                    As[buf][a_word8(c0 + j, r0)] = f2tf(av[j]);
                    Bs[buf][b_word8(c0 + j, r0)] = f2tf(bv[j]);
                }
            }
            __syncthreads();
        }
    }

    const int gid = lane >> 2;
    const int tig = lane & 3;
#pragma unroll
    for (int mt = 0; mt < 4; ++mt) {
        const long long row = bm + (wm + mt) * 16 + gid;
#pragma unroll
        for (int nt = 0; nt < 4; ++nt) {
            const int col = bn + (wn + nt) * 8 + tig * 2;
            if (RED) {
                atomicAdd(C + row * ldc + col,             acc[mt][nt][0]);
                atomicAdd(C + row * ldc + col + 1,         acc[mt][nt][1]);
                atomicAdd(C + (row + 8) * ldc + col,       acc[mt][nt][2]);
                atomicAdd(C + (row + 8) * ldc + col + 1,   acc[mt][nt][3]);
            } else {
                *(float2*)(C + row * ldc + col) = make_float2(acc[mt][nt][0], acc[mt][nt][1]);
                *(float2*)(C + (row + 8) * ldc + col) = make_float2(acc[mt][nt][2], acc[mt][nt][3]);
            }
        }
    }
}

// Generic strided-batch wrapper (CMODE: 0 plain, 1 causal tile-skip)
template<bool TN, int CMODE>
__global__ __launch_bounds__(256, 2) void gemm_tf32(
    const float* __restrict__ A, const float* __restrict__ B, float* __restrict__ C,
    int K, int lda, int ldb, int ldc,
    long long sA, long long sB, long long sC)
{
    const int bm = blockIdx.y * 128;
    const int bn = blockIdx.x * 128;
    if (CMODE == 1 && bn > bm) return;
    tf32_body<TN, false>(A + (long long)blockIdx.z * sA,
                         B + (long long)blockIdx.z * sB,
                         C + (long long)blockIdx.z * sC,
                         0, K, lda, ldb, ldc, bm, bn);
}

// Down-projections, split-K x2: z = sel*2 + khalf; RED epilogue into zeroed C.
__global__ __launch_bounds__(256, 2) void gemm_down_split(
    const float* __restrict__ h, const float* __restrict__ w_dkv,
    const float* __restrict__ w_dq, float* __restrict__ ckv, float* __restrict__ cq)
{
    const int sel = blockIdx.z >> 1;
    const int kh = blockIdx.z & 1;
    const float* B = sel ? w_dq : w_dkv;
    float* C = sel ? cq : ckv;
    tf32_body<false, true>(h, B, C, kh * (D / 2), (kh + 1) * (D / 2),
                           D, D, DC, blockIdx.y * 128, blockIdx.x * 128);
}

// Attention output, split-K x2 over the causal range [bm, T):
// grid (2, 16, NH): x = khalf, y = l-tile, z = head. RED epilogue.
__global__ __launch_bounds__(256, 2) void gemm_attn_split(
    const float* __restrict__ logits, const float* __restrict__ v, float* __restrict__ attn)
{
    const int bm = blockIdx.y * 128;
    const int half = (T - bm) >> 1;              // multiple of 64
    const int kbeg = bm + blockIdx.x * half;
    const int kend = kbeg + half;
    const long long z = blockIdx.z;
    tf32_body<true, true>(logits + z * T * T, v + z * T * DH, attn + z * DH,
                          kbeg, kend, T, DH, NH * DH, bm, 0);
}

// Zero-fill (float4)
__global__ void zero_f4(float4* p, int n4)
{
    int i = blockIdx.x * blockDim.x + threadIdx.x;
    if (i < n4) p[i] = make_float4(0.f, 0.f, 0.f, 0.f);
}

// ============================================================
// 64x64 fp32 GEMM (N=64 cases: k_r, q_r) — FFMA2 mainloop
// ============================================================
#define SM_ 64
#define SK_ 16
__global__ __launch_bounds__(256) void gemm_nt64(
    const float* __restrict__ A, const float* __restrict__ B, float* __restrict__ C,
    int K, int lda, int ldb, int ldc,
    long long sA, long long sB, long long sC)
{
    __shared__ float As[SK_][SM_];
    __shared__ float Bs[SK_][SM_];
    A += (long long)blockIdx.z * sA;
    B += (long long)blockIdx.z * sB;
    C += (long long)blockIdx.z * sC;
    const int bm = blockIdx.y * SM_;
    const int bn = blockIdx.x * SM_;
    const int tid = threadIdx.x;
    const int tx = tid & 15;
    const int ty = tid >> 4;
    const int lrow = tid >> 2;
    const int lcol = (tid & 3) * 4;

    ull acc2[2][4] = {};

    for (int k0 = 0; k0 < K; k0 += SK_) {
        float4 a = *(const float4*)(A + (long long)(bm + lrow) * lda + k0 + lcol);
        float4 b = *(const float4*)(B + (long long)(bn + lrow) * ldb + k0 + lcol);
        __syncthreads();
        As[lcol + 0][lrow] = a.x; As[lcol + 1][lrow] = a.y;
        As[lcol + 2][lrow] = a.z; As[lcol + 3][lrow] = a.w;
        Bs[lcol + 0][lrow] = b.x; Bs[lcol + 1][lrow] = b.y;
        Bs[lcol + 2][lrow] = b.z; Bs[lcol + 3][lrow] = b.w;
        __syncthreads();
#pragma unroll
        for (int kk = 0; kk < SK_; ++kk) {
            float4 av = *(const float4*)(&As[kk][ty * 4]);
            float4 bv = *(const float4*)(&Bs[kk][tx * 4]);
            ull ap[2];
            ap[0] = ((const ull*)&av)[0];
            ap[1] = ((const ull*)&av)[1];
            ull bb[4];
            bb[0] = dup2(bv.x); bb[1] = dup2(bv.y);
            bb[2] = dup2(bv.z); bb[3] = dup2(bv.w);
#pragma unroll
            for (int p = 0; p < 2; ++p)
#pragma unroll
                for (int j = 0; j < 4; ++j)
                    ffma2(acc2[p][j], ap[p], bb[j]);
        }
    }

#pragma unroll
    for (int p = 0; p < 2; ++p) {
#pragma unroll
        for (int half = 0; half < 2; ++half) {
            const int crow = bm + ty * 4 + p * 2 + half;
            F2u v0, v1, v2, v3;
            v0.u = acc2[p][0]; v1.u = acc2[p][1];
            v2.u = acc2[p][2]; v3.u = acc2[p][3];
            float4 o = half ? make_float4(v0.f.y, v1.f.y, v2.f.y, v3.f.y)
                            : make_float4(v0.f.x, v1.f.x, v2.f.x, v3.f.x);
            *(float4*)(C + (long long)crow * ldc + bn + tx * 4) = o;
        }
    }
}

// ============================================================
// Elementwise kernels
// ============================================================
__global__ void rope_q_kernel(float* __restrict__ q, const float* __restrict__ freqs)
{
    int idx = blockIdx.x * blockDim.x + threadIdx.x;   // NH*T*32
    int i = idx & 31;
    int t = (idx >> 5) & (T - 1);
    int n = idx >> 16;
    float ang = freqs[t * (DRH / 2) + i];
    float c, s;
    __sincosf(ang, &s, &c);
    float* base = q + ((size_t)(n * T + t)) * QKD + DH;
    float re = base[i], im = base[i + 32];
    base[i]      = re * c - im * s;
    base[i + 32] = re * s + im * c;
}

__global__ void rope_k_bcast_kernel(const float* __restrict__ kr, float* __restrict__ kbuf,
                                    const float* __restrict__ freqs)
{
    int idx = blockIdx.x * blockDim.x + threadIdx.x;   // T*32
    int i = idx & 31;
    int t = idx >> 5;
    float ang = freqs[t * (DRH / 2) + i];
    float c, s;
    __sincosf(ang, &s, &c);
    float re = kr[t * DRH + i], im = kr[t * DRH + 32 + i];
    const float inv_nh = 1.0f / (float)NH;
    float rr = (re * c - im * s) * inv_nh;
    float ri = (re * s + im * c) * inv_nh;
#pragma unroll
    for (int n = 0; n < NH; ++n) {
        float* b = kbuf + ((size_t)(n * T + t)) * QKD + DH;
        b[i]      = rr;
        b[i + 32] = ri;
    }
}

__global__ void wo_transpose_kernel(const float* __restrict__ wo, float* __restrict__ wt)
{
    int idx = blockIdx.x * blockDim.x + threadIdx.x;   // D * NH * DH
    int j = idx & (NH * DH - 1);
    int d = idx >> 11;
    int n = j >> 7;
    int e = j & (DH - 1);
    wt[idx] = wo[(size_t)d * (DH * NH) + e * NH + n];
}

// Causal softmax: row t over l, analytic mask (l<=t valid), zeros elsewhere.
__global__ __launch_bounds__(256) void softmax_kernel(
    float* __restrict__ logits, float scale)
{
    const int t = blockIdx.x;
    const int n = blockIdx.y;
    float* __restrict__ row = logits + ((size_t)n * T + t) * T;
    const int tid = threadIdx.x;
    const int wbase = tid & ~31;

    float v[8];
    float mx = -1e30f;
#pragma unroll
    for (int j = 0; j < 8; ++j) {
        const int l = tid + j * 256;
        if (wbase + j * 256 > t) {
            v[j] = -1e30f;
        } else {
            float x = row[l];
            v[j] = (l <= t) ? x * scale : -1e30f;
        }
        mx = fmaxf(mx, v[j]);
    }
    __shared__ float redm[8], reds[8];
#pragma unroll
    for (int o = 16; o; o >>= 1) mx = fmaxf(mx, __shfl_xor_sync(0xffffffffu, mx, o));
    if ((tid & 31) == 0) redm[tid >> 5] = mx;
    __syncthreads();
    mx = redm[0];
#pragma unroll
    for (int w = 1; w < 8; ++w) mx = fmaxf(mx, redm[w]);

    float sum = 0.0f;
#pragma unroll
    for (int j = 0; j < 8; ++j) {
        if (v[j] > -1e29f) {
            v[j] = __expf(v[j] - mx);
            sum += v[j];
        } else {
            v[j] = 0.0f;
        }
    }
#pragma unroll
    for (int o = 16; o; o >>= 1) sum += __shfl_xor_sync(0xffffffffu, sum, o);
    if ((tid & 31) == 0) reds[tid >> 5] = sum;
    __syncthreads();
    sum = reds[0];
#pragma unroll
    for (int w = 1; w < 8; ++w) sum += reds[w];

    float inv = 1.0f / sum;
#pragma unroll
    for (int j = 0; j < 8; ++j)
        row[tid + j * 256] = v[j] * inv;
}

// ============================================================
// Launch
// ============================================================
extern "C" void kernel_launch(void* const* d_in, const int* in_sizes, int n_in,
                              void* d_out, int out_size)
{
    const float* h     = (const float*)d_in[0];
    const float* freqs = (const float*)d_in[1];
    const float* w_dkv = (const float*)d_in[3];
    const float* w_uk  = (const float*)d_in[4];
    const float* w_uv  = (const float*)d_in[5];
    const float* w_dq  = (const float*)d_in[6];
    const float* w_uq  = (const float*)d_in[7];
    const float* w_qr  = (const float*)d_in[8];
    const float* w_kr  = (const float*)d_in[9];
    const float* w_o   = (const float*)d_in[10];
    float* out = (float*)d_out;
    (void)in_sizes; (void)n_in; (void)out_size;

    float *ckv, *cq, *q, *k, *v, *kr, *logits, *attn, *wot;
    cudaGetSymbolAddress((void**)&ckv,    g_ckv);
    cudaGetSymbolAddress((void**)&cq,     g_cq);
    cudaGetSymbolAddress((void**)&q,      g_q);
    cudaGetSymbolAddress((void**)&k,      g_k);
    cudaGetSymbolAddress((void**)&v,      g_v);
    cudaGetSymbolAddress((void**)&kr,     g_kr);
    cudaGetSymbolAddress((void**)&logits, g_logits);
    cudaGetSymbolAddress((void**)&attn,   g_attn);
    cudaGetSymbolAddress((void**)&wot,    g_wot);

    const dim3 blk(256);
    const long long sQ = (long long)T * QKD;

    // Zero split-K accumulation targets
    zero_f4<<<(T * DC / 4 + 255) / 256, 256>>>((float4*)ckv, T * DC / 4);
    zero_f4<<<(T * DC / 4 + 255) / 256, 256>>>((float4*)cq,  T * DC / 4);
    zero_f4<<<(T * NH * DH / 4 + 255) / 256, 256>>>((float4*)attn, T * NH * DH / 4);

    // Latents: c_kv + c_q, split-K x2 (256 blocks, K=1024 each)
    gemm_down_split<<<dim3(DC / 128, T / 128, 4), blk>>>(h, w_dkv, w_dq, ckv, cq);
    // k_r (pre-rope): N=64, fp32
    gemm_nt64<<<dim3(1, T / SM_, 1), 256>>>(h, w_kr, kr, D, D, D, DRH, 0, 0, 0);

    // Per-head up-projections
    gemm_tf32<false, 0><<<dim3(1, T / 128, NH), blk>>>(ckv, w_uk, k, DC, DC, NH * DC, QKD, 0, DC, sQ);
    gemm_tf32<false, 0><<<dim3(1, T / 128, NH), blk>>>(ckv, w_uv, v, DC, DC, NH * DC, DH,  0, DC, (long long)T * DH);
    gemm_tf32<false, 0><<<dim3(1, T / 128, NH), blk>>>(cq,  w_uq, q, DC, DC, NH * DC, QKD, 0, DC, sQ);
    // q_r: N=64, fp32
    gemm_nt64<<<dim3(1, T / SM_, NH), 256>>>(cq, w_qr, q + DH, DC, DC, NH * DC, QKD, 0, DC, sQ);

    // Rope
    rope_q_kernel<<<(NH * T * 32) / 256, 256>>>(q, freqs);
    rope_k_bcast_kernel<<<(T * 32) / 256, 256>>>(kr, k, freqs);

    // logits[n,t,l] = q . k  — skip fully-masked upper tiles
    gemm_tf32<false, 1><<<dim3(T / 128, T / 128, NH), blk>>>(q, k, logits, QKD, QKD, QKD, T, sQ, sQ, (long long)T * T);

    // causal softmax, scale = 1/sqrt(192); writes exact zeros for l > t
    softmax_kernel<<<dim3(T, NH), 256>>>(logits, 0.07216878364870323f);

    // out[n,l,e] = sum_{t>=l} S[n,t,l] v[n,t,e] — split-K x2 over causal range
    gemm_attn_split<<<dim3(2, T / 128, NH), blk>>>(logits, v, attn);

    // w_o permute then final projection
    wo_transpose_kernel<<<(D * NH * DH) / 256, 256>>>(w_o, wot);
    gemm_tf32<false, 0><<<dim3(D / 128, T / 128, 1), blk>>>(attn, wot, out, NH * DH, NH * DH, NH * DH, D, 0, 0, 0);
}